// round 13
// baseline (speedup 1.0000x reference)
#include <cuda_runtime.h>
#include <cuda_bf16.h>
#include <math.h>
#include <stdint.h>

#define N_TOK 131072
#define C_DIM 256
#define HID_DIM 1024
#define H_HEADS 8
#define D_HEAD 32
#define K_WIN 128
#define P_TILES (N_TOK / K_WIN)
#define SCALE_ATTN 0.17677669529663687f

typedef __nv_bfloat16 bf16;

// ---------------- scratch (device globals) ----------------
__device__ bf16  g_ln[N_TOK * C_DIM];
__device__ bf16  g_attn[N_TOK * C_DIM];
__device__ float g_x[N_TOK * C_DIM];
__device__ bf16  g_mid[N_TOK * HID_DIM];
__device__ bf16  g_wqkvT[3 * C_DIM * C_DIM];
__device__ bf16  g_wprojT[C_DIM * C_DIM];
__device__ bf16  g_w1T[HID_DIM * C_DIM];
__device__ bf16  g_w2T[C_DIM * HID_DIM];

// ---------------- PTX helpers (plain sm_103-safe) ----------
__device__ __forceinline__ uint32_t smem_u32(const void* p) {
    uint32_t a;
    asm("{ .reg .u64 t; cvta.to.shared.u64 t, %1; cvt.u32.u64 %0, t; }" : "=r"(a) : "l"(p));
    return a;
}
#define CP_ASYNC16(dst, src) \
    asm volatile("cp.async.cg.shared.global [%0], [%1], 16;" :: "r"(dst), "l"(src))
#define CP_COMMIT() asm volatile("cp.async.commit_group;" ::: "memory")
#define CP_WAIT(n)  asm volatile("cp.async.wait_group %0;" :: "n"(n) : "memory")

#define LDMATRIX_X4(r0, r1, r2, r3, addr) \
    asm volatile("ldmatrix.sync.aligned.m8n8.x4.shared.b16 {%0,%1,%2,%3}, [%4];" \
                 : "=r"(r0), "=r"(r1), "=r"(r2), "=r"(r3) : "r"(addr))
#define LDMATRIX_X4_T(r0, r1, r2, r3, addr) \
    asm volatile("ldmatrix.sync.aligned.m8n8.x4.trans.shared.b16 {%0,%1,%2,%3}, [%4];" \
                 : "=r"(r0), "=r"(r1), "=r"(r2), "=r"(r3) : "r"(addr))

#define MMA_BF16(c, a, b0, b1) \
    asm volatile("mma.sync.aligned.m16n8k16.row.col.f32.bf16.bf16.f32 " \
                 "{%0,%1,%2,%3}, {%4,%5,%6,%7}, {%8,%9}, {%0,%1,%2,%3};" \
                 : "+f"((c)[0]), "+f"((c)[1]), "+f"((c)[2]), "+f"((c)[3]) \
                 : "r"((a)[0]), "r"((a)[1]), "r"((a)[2]), "r"((a)[3]), \
                   "r"(b0), "r"(b1))

__device__ __forceinline__ float gelu_tanh(float x) {
    float x3 = x * x * x;
    float t = tanhf(0.7978845608028654f * (x + 0.044715f * x3));
    return 0.5f * x * (1.0f + t);
}
__device__ __forceinline__ uint32_t packbf(float x, float y) {
    __nv_bfloat162 t = __float22bfloat162_rn(make_float2(x, y));
    return *(uint32_t*)&t;
}

// ---------- merged prep: ln1 (blocks 0..16383) + weight prep (rest) --------
__global__ void prep_kernel(const float* __restrict__ x, const float* __restrict__ g,
                            const float* __restrict__ b, bf16* __restrict__ y,
                            const float* __restrict__ wqkv, const float* __restrict__ wproj,
                            const float* __restrict__ w1, const float* __restrict__ w2,
                            bf16* __restrict__ o_qkv, bf16* __restrict__ o_proj,
                            bf16* __restrict__ o_w1, bf16* __restrict__ o_w2) {
    if (blockIdx.x < 16384) {
        int row = blockIdx.x * 8 + (threadIdx.x >> 5);
        int lane = threadIdx.x & 31;
        const float4* xr = (const float4*)(x + (size_t)row * C_DIM);
        float4 v0 = xr[lane * 2];
        float4 v1 = xr[lane * 2 + 1];
        float s = v0.x + v0.y + v0.z + v0.w + v1.x + v1.y + v1.z + v1.w;
        float ss = v0.x*v0.x + v0.y*v0.y + v0.z*v0.z + v0.w*v0.w
                 + v1.x*v1.x + v1.y*v1.y + v1.z*v1.z + v1.w*v1.w;
        #pragma unroll
        for (int o = 16; o > 0; o >>= 1) {
            s  += __shfl_xor_sync(0xffffffffu, s,  o);
            ss += __shfl_xor_sync(0xffffffffu, ss, o);
        }
        float mu = s * (1.0f / C_DIM);
        float var = ss * (1.0f / C_DIM) - mu * mu;
        float rstd = rsqrtf(var + 1e-5f);
        const float4* g4 = (const float4*)g;
        const float4* b4 = (const float4*)b;
        float4 ga = g4[lane * 2], gb = g4[lane * 2 + 1];
        float4 ba = b4[lane * 2], bb = b4[lane * 2 + 1];
        float o[8];
        o[0] = (v0.x - mu) * rstd * ga.x + ba.x;
        o[1] = (v0.y - mu) * rstd * ga.y + ba.y;
        o[2] = (v0.z - mu) * rstd * ga.z + ba.z;
        o[3] = (v0.w - mu) * rstd * ga.w + ba.w;
        o[4] = (v1.x - mu) * rstd * gb.x + bb.x;
        o[5] = (v1.y - mu) * rstd * gb.y + bb.y;
        o[6] = (v1.z - mu) * rstd * gb.z + bb.z;
        o[7] = (v1.w - mu) * rstd * gb.w + bb.w;
        uint32_t pk[4];
        #pragma unroll
        for (int i = 0; i < 4; i++) pk[i] = packbf(o[2*i], o[2*i+1]);
        *(uint4*)(y + (size_t)row * C_DIM + lane * 8) = make_uint4(pk[0], pk[1], pk[2], pk[3]);
    } else {
        int idx = (blockIdx.x - 16384) * 256 + threadIdx.x;
        if (idx < 196608) {
            int n = idx / 256, k = idx % 256;
            o_qkv[idx] = __float2bfloat16(wqkv[k * 768 + n]);
        } else if (idx < 262144) {
            int i = idx - 196608;
            int n = i / 256, k = i % 256;
            o_proj[i] = __float2bfloat16(wproj[k * 256 + n]);
        } else if (idx < 524288) {
            int i = idx - 262144;
            int n = i / 256, k = i % 256;
            o_w1[i] = __float2bfloat16(w1[k * 1024 + n]);
        } else {
            int i = idx - 524288;
            int n = i / 1024, k = i % 1024;
            o_w2[i] = __float2bfloat16(w2[k * 256 + n]);
        }
    }
}

// ---------------- layernorm f32 -> bf16 (ln2) ----------------
__global__ void ln_kernel(const float* __restrict__ x, const float* __restrict__ g,
                          const float* __restrict__ b, bf16* __restrict__ y) {
    int row = blockIdx.x * 8 + threadIdx.y;
    int lane = threadIdx.x;
    const float4* xr = (const float4*)(x + (size_t)row * C_DIM);
    float4 v0 = xr[lane * 2];
    float4 v1 = xr[lane * 2 + 1];
    float s = v0.x + v0.y + v0.z + v0.w + v1.x + v1.y + v1.z + v1.w;
    float ss = v0.x*v0.x + v0.y*v0.y + v0.z*v0.z + v0.w*v0.w
             + v1.x*v1.x + v1.y*v1.y + v1.z*v1.z + v1.w*v1.w;
    #pragma unroll
    for (int o = 16; o > 0; o >>= 1) {
        s  += __shfl_xor_sync(0xffffffffu, s,  o);
        ss += __shfl_xor_sync(0xffffffffu, ss, o);
    }
    float mu = s * (1.0f / C_DIM);
    float var = ss * (1.0f / C_DIM) - mu * mu;
    float rstd = rsqrtf(var + 1e-5f);
    const float4* g4 = (const float4*)g;
    const float4* b4 = (const float4*)b;
    float4 ga = g4[lane * 2], gb = g4[lane * 2 + 1];
    float4 ba = b4[lane * 2], bb = b4[lane * 2 + 1];
    float o[8];
    o[0] = (v0.x - mu) * rstd * ga.x + ba.x;
    o[1] = (v0.y - mu) * rstd * ga.y + ba.y;
    o[2] = (v0.z - mu) * rstd * ga.z + ba.z;
    o[3] = (v0.w - mu) * rstd * ga.w + ba.w;
    o[4] = (v1.x - mu) * rstd * gb.x + bb.x;
    o[5] = (v1.y - mu) * rstd * gb.y + bb.y;
    o[6] = (v1.z - mu) * rstd * gb.z + bb.z;
    o[7] = (v1.w - mu) * rstd * gb.w + bb.w;
    uint32_t pk[4];
    #pragma unroll
    for (int i = 0; i < 4; i++) pk[i] = packbf(o[2*i], o[2*i+1]);
    *(uint4*)(y + (size_t)row * C_DIM + lane * 8) = make_uint4(pk[0], pk[1], pk[2], pk[3]);
}

// ------- HMMA GEMM (round-7 config, compile-time K, fully unrolled) --------
// BM=128, BN=128, BK=64, 256 thr (8 warps 2x4), warp tile 64x32, 2 CTA/SM.
#define G_LDS 72
#define G_STAGE (2 * 128 * G_LDS)
#define G_SMEM (3 * G_STAGE * 2)

template <int EPI, bool OF32, int KK>
__global__ void __launch_bounds__(256, 2)
gemm_mma(const bf16* __restrict__ A, const bf16* __restrict__ BT,
         const float* __restrict__ bias, const float* __restrict__ res,
         void* __restrict__ Cout, int Nn) {
    constexpr int BK = 64;
    constexpr int NK = KK / BK;
    extern __shared__ bf16 smbuf[];

    const int tid = threadIdx.x;
    const int wid = tid >> 5, lane = tid & 31;
    const int wm = wid & 1, wn = wid >> 1;
    const int row0 = blockIdx.y * 128;
    const int col0 = blockIdx.x * 128;

    float acc[4][4][4];
    #pragma unroll
    for (int mi = 0; mi < 4; mi++)
        #pragma unroll
        for (int ni = 0; ni < 4; ni++)
            #pragma unroll
            for (int e = 0; e < 4; e++) acc[mi][ni][e] = 0.0f;

    auto load_stage = [&](int s, int k0) {
        bf16* As = smbuf + s * G_STAGE;
        bf16* Bs = As + 128 * G_LDS;
        #pragma unroll
        for (int i = 0; i < 4; i++) {
            int idx = tid + i * 256;
            int r = idx >> 3, c = (idx & 7) * 8;
            CP_ASYNC16(smem_u32(As + r * G_LDS + c), A + (size_t)(row0 + r) * KK + k0 + c);
        }
        #pragma unroll
        for (int i = 0; i < 4; i++) {
            int idx = tid + i * 256;
            int r = idx >> 3, c = (idx & 7) * 8;
            CP_ASYNC16(smem_u32(Bs + r * G_LDS + c), BT + (size_t)(col0 + r) * KK + k0 + c);
        }
    };

    load_stage(0, 0); CP_COMMIT();
    load_stage(1, BK); CP_COMMIT();

    #pragma unroll
    for (int kt = 0; kt < NK; kt++) {
        if (kt < NK - 1) CP_WAIT(1); else CP_WAIT(0);
        __syncthreads();
        if (kt + 2 < NK) { load_stage((kt + 2) % 3, (kt + 2) * BK); CP_COMMIT(); }

        bf16* As = smbuf + (kt % 3) * G_STAGE;
        bf16* Bs = As + 128 * G_LDS;
        #pragma unroll
        for (int ks = 0; ks < 4; ks++) {
            const int k0 = ks * 16;
            uint32_t a[4][4];
            #pragma unroll
            for (int mi = 0; mi < 4; mi++) {
                int r = wm * 64 + mi * 16 + (lane & 15);
                int c = k0 + ((lane >> 4) << 3);
                LDMATRIX_X4(a[mi][0], a[mi][1], a[mi][2], a[mi][3],
                            smem_u32(As + r * G_LDS + c));
            }
            uint32_t b[4][2];
            #pragma unroll
            for (int bi = 0; bi < 2; bi++) {
                int r = wn * 32 + bi * 16 + (lane & 15);
                int c = k0 + ((lane >> 4) << 3);
                uint32_t r0, r1, r2, r3;
                LDMATRIX_X4(r0, r1, r2, r3, smem_u32(Bs + r * G_LDS + c));
                b[2*bi][0] = r0; b[2*bi][1] = r2;
                b[2*bi+1][0] = r1; b[2*bi+1][1] = r3;
            }
            #pragma unroll
            for (int mi = 0; mi < 4; mi++)
                #pragma unroll
                for (int ni = 0; ni < 4; ni++)
                    MMA_BF16(acc[mi][ni], a[mi], b[ni][0], b[ni][1]);
        }
    }

    #pragma unroll
    for (int mi = 0; mi < 4; mi++) {
        #pragma unroll
        for (int ni = 0; ni < 4; ni++) {
            int r0 = row0 + wm * 64 + mi * 16 + (lane >> 2);
            int cc = col0 + wn * 32 + ni * 8 + (lane & 3) * 2;
            float2 bv = *(const float2*)(bias + cc);
            #pragma unroll
            for (int half = 0; half < 2; half++) {
                int r = r0 + half * 8;
                float vx = acc[mi][ni][2*half]   + bv.x;
                float vy = acc[mi][ni][2*half+1] + bv.y;
                if (EPI == 1) { vx = gelu_tanh(vx); vy = gelu_tanh(vy); }
                if (EPI == 2) {
                    float2 rv = *(const float2*)(res + (size_t)r * Nn + cc);
                    vx += rv.x; vy += rv.y;
                }
                if (OF32) {
                    *(float2*)((float*)Cout + (size_t)r * Nn + cc) = make_float2(vx, vy);
                } else {
                    *(uint32_t*)((bf16*)Cout + (size_t)r * Nn + cc) = packbf(vx, vy);
                }
            }
        }
    }
}

// ---------------- fused qkv-GEMM + attention (round-7 champion) ------------
#define FA_SMEM 200192

__global__ void __launch_bounds__(256)
fused_qkv_attn(const bf16* __restrict__ lnin, const bf16* __restrict__ wqkvT,
               const float* __restrict__ bqkv, const int* __restrict__ order,
               bf16* __restrict__ out) {
    extern __shared__ char sm[];
    bf16* pA = (bf16*)(sm);
    bf16* pW = (bf16*)(sm + 67584);
    bf16* pQ = (bf16*)(sm + 168960);
    bf16* pK = (bf16*)(sm + 179200);
    bf16* pV = (bf16*)(sm + 189440);
    int*  ptok = (int*)(sm + 199680);

    const int p = blockIdx.x;
    const int tid = threadIdx.x, wid = tid >> 5, lane = tid & 31;
    const int m0 = wid * 16;

    if (tid < 128) ptok[tid] = order[p * K_WIN + tid];

    #pragma unroll
    for (int i = 0; i < 16; i++) {
        int ch = tid + i * 256;
        int r = ch >> 5, c = (ch & 31) * 8;
        int token = order[p * K_WIN + r];
        CP_ASYNC16(smem_u32(pA + r * 264 + c), lnin + (size_t)token * C_DIM + c);
    }
    auto load_w = [&](int s, int h) {
        bf16* dst = pW + s * 25344;
        #pragma unroll
        for (int i = 0; i < 12; i++) {
            int ch = tid + i * 256;
            int r = ch >> 5, c = (ch & 31) * 8;
            int row_g = (r >> 5) * 256 + h * 32 + (r & 31);
            CP_ASYNC16(smem_u32(dst + r * 264 + c), wqkvT + (size_t)row_g * C_DIM + c);
        }
    };
    load_w(0, 0);
    CP_COMMIT();

    for (int h = 0; h < H_HEADS; h++) {
        if (h < H_HEADS - 1) { load_w((h + 1) & 1, h + 1); CP_COMMIT(); }
        if (h < H_HEADS - 1) CP_WAIT(1); else CP_WAIT(0);
        __syncthreads();

        float acc[12][4];
        #pragma unroll
        for (int j = 0; j < 12; j++)
            #pragma unroll
            for (int e = 0; e < 4; e++) acc[j][e] = 0.0f;
        const bf16* Wb = pW + (h & 1) * 25344;
        #pragma unroll
        for (int kk = 0; kk < 16; kk++) {
            const int k0 = kk * 16;
            uint32_t a[4];
            LDMATRIX_X4(a[0], a[1], a[2], a[3],
                        smem_u32(pA + (m0 + (lane & 15)) * 264 + k0 + ((lane >> 4) << 3)));
            #pragma unroll
            for (int nt = 0; nt < 6; nt++) {
                uint32_t r0, r1, r2, r3;
                LDMATRIX_X4(r0, r1, r2, r3,
                            smem_u32(Wb + (nt * 16 + (lane & 15)) * 264 + k0 + ((lane >> 4) << 3)));
                MMA_BF16(acc[2*nt],   a, r0, r2);
                MMA_BF16(acc[2*nt+1], a, r1, r3);
            }
        }
        {
            int rr = m0 + (lane >> 2);
            #pragma unroll
            for (int j = 0; j < 12; j++) {
                int n = j * 8 + (lane & 3) * 2;
                int sel = n >> 5, d = n & 31;
                float2 bv = *(const float2*)(bqkv + sel * 256 + h * 32 + d);
                bf16* dst = (sel == 0) ? pQ : (sel == 1) ? pK : pV;
                *(uint32_t*)(dst + rr * 40 + d)       = packbf(acc[j][0] + bv.x, acc[j][1] + bv.y);
                *(uint32_t*)(dst + (rr + 8) * 40 + d) = packbf(acc[j][2] + bv.x, acc[j][3] + bv.y);
            }
        }
        __syncthreads();

        float sacc[16][4];
        #pragma unroll
        for (int nt = 0; nt < 16; nt++)
            #pragma unroll
            for (int e = 0; e < 4; e++) sacc[nt][e] = 0.0f;
        #pragma unroll
        for (int ksx = 0; ksx < 2; ksx++) {
            const int k0 = ksx * 16;
            uint32_t a[4];
            LDMATRIX_X4(a[0], a[1], a[2], a[3],
                        smem_u32(pQ + (m0 + (lane & 15)) * 40 + k0 + ((lane >> 4) << 3)));
            #pragma unroll
            for (int t = 0; t < 8; t++) {
                uint32_t r0, r1, r2, r3;
                LDMATRIX_X4(r0, r1, r2, r3,
                            smem_u32(pK + (t * 16 + (lane & 15)) * 40 + k0 + ((lane >> 4) << 3)));
                MMA_BF16(sacc[2*t],   a, r0, r2);
                MMA_BF16(sacc[2*t+1], a, r1, r3);
            }
        }

        float m_lo = -INFINITY, m_hi = -INFINITY;
        #pragma unroll
        for (int nt = 0; nt < 16; nt++) {
            #pragma unroll
            for (int e = 0; e < 4; e++) sacc[nt][e] *= SCALE_ATTN;
            m_lo = fmaxf(m_lo, fmaxf(sacc[nt][0], sacc[nt][1]));
            m_hi = fmaxf(m_hi, fmaxf(sacc[nt][2], sacc[nt][3]));
        }
        m_lo = fmaxf(m_lo, __shfl_xor_sync(0xffffffffu, m_lo, 1));
        m_lo = fmaxf(m_lo, __shfl_xor_sync(0xffffffffu, m_lo, 2));
        m_hi = fmaxf(m_hi, __shfl_xor_sync(0xffffffffu, m_hi, 1));
        m_hi = fmaxf(m_hi, __shfl_xor_sync(0xffffffffu, m_hi, 2));

        float l_lo = 0.0f, l_hi = 0.0f;
        uint32_t pf[16][2];
        #pragma unroll
        for (int nt = 0; nt < 16; nt++) {
            float e0 = __expf(sacc[nt][0] - m_lo);
            float e1 = __expf(sacc[nt][1] - m_lo);
            float e2 = __expf(sacc[nt][2] - m_hi);
            float e3 = __expf(sacc[nt][3] - m_hi);
            l_lo += e0 + e1;
            l_hi += e2 + e3;
            pf[nt][0] = packbf(e0, e1);
            pf[nt][1] = packbf(e2, e3);
        }
        l_lo += __shfl_xor_sync(0xffffffffu, l_lo, 1);
        l_lo += __shfl_xor_sync(0xffffffffu, l_lo, 2);
        l_hi += __shfl_xor_sync(0xffffffffu, l_hi, 1);
        l_hi += __shfl_xor_sync(0xffffffffu, l_hi, 2);

        float acco[4][4];
        #pragma unroll
        for (int nt = 0; nt < 4; nt++)
            #pragma unroll
            for (int e = 0; e < 4; e++) acco[nt][e] = 0.0f;
        #pragma unroll
        for (int kk = 0; kk < 8; kk++) {
            uint32_t a[4] = {pf[2*kk][0], pf[2*kk][1], pf[2*kk+1][0], pf[2*kk+1][1]};
            uint32_t r0, r1, r2, r3;
            LDMATRIX_X4_T(r0, r1, r2, r3,
                          smem_u32(pV + (kk * 16 + (lane & 15)) * 40 + ((lane >> 4) << 3)));
            MMA_BF16(acco[0], a, r0, r1);
            MMA_BF16(acco[1], a, r2, r3);
            uint32_t s0, s1, s2, s3;
            LDMATRIX_X4_T(s0, s1, s2, s3,
                          smem_u32(pV + (kk * 16 + (lane & 15)) * 40 + 16 + ((lane >> 4) << 3)));
            MMA_BF16(acco[2], a, s0, s1);
            MMA_BF16(acco[3], a, s2, s3);
        }

        float inv_lo = 1.0f / l_lo, inv_hi = 1.0f / l_hi;
        int r_lo = m0 + (lane >> 2);
        int tok_lo = ptok[r_lo], tok_hi = ptok[r_lo + 8];
        bf16* o_lo = out + (size_t)tok_lo * C_DIM + h * D_HEAD + (lane & 3) * 2;
        bf16* o_hi = out + (size_t)tok_hi * C_DIM + h * D_HEAD + (lane & 3) * 2;
        #pragma unroll
        for (int nt = 0; nt < 4; nt++) {
            *(uint32_t*)(o_lo + nt * 8) = packbf(acco[nt][0] * inv_lo, acco[nt][1] * inv_lo);
            *(uint32_t*)(o_hi + nt * 8) = packbf(acco[nt][2] * inv_hi, acco[nt][3] * inv_hi);
        }
    }
}

// ---------------------------- launch ---------------------------------------
extern "C" void kernel_launch(void* const* d_in, const int* in_sizes, int n_in,
                              void* d_out, int out_size) {
    const float* feat   = (const float*)d_in[0];
    const float* ln1_g  = (const float*)d_in[1];
    const float* ln1_b  = (const float*)d_in[2];
    const float* w_qkv  = (const float*)d_in[3];
    const float* b_qkv  = (const float*)d_in[4];
    const float* w_proj = (const float*)d_in[5];
    const float* b_proj = (const float*)d_in[6];
    const float* ln2_g  = (const float*)d_in[7];
    const float* ln2_b  = (const float*)d_in[8];
    const float* w1     = (const float*)d_in[9];
    const float* b1     = (const float*)d_in[10];
    const float* w2     = (const float*)d_in[11];
    const float* b2     = (const float*)d_in[12];
    const int*   order  = (const int*)d_in[13];

    bf16 *p_ln, *p_attn, *p_mid, *p_wqkvT, *p_wprojT, *p_w1T, *p_w2T;
    float* p_x;
    cudaGetSymbolAddress((void**)&p_ln,     g_ln);
    cudaGetSymbolAddress((void**)&p_attn,   g_attn);
    cudaGetSymbolAddress((void**)&p_x,      g_x);
    cudaGetSymbolAddress((void**)&p_mid,    g_mid);
    cudaGetSymbolAddress((void**)&p_wqkvT,  g_wqkvT);
    cudaGetSymbolAddress((void**)&p_wprojT, g_wprojT);
    cudaGetSymbolAddress((void**)&p_w1T,    g_w1T);
    cudaGetSymbolAddress((void**)&p_w2T,    g_w2T);

    cudaFuncSetAttribute(fused_qkv_attn, cudaFuncAttributeMaxDynamicSharedMemorySize, FA_SMEM);
    cudaFuncSetAttribute(gemm_mma<2, true, 256>,   cudaFuncAttributeMaxDynamicSharedMemorySize, G_SMEM);
    cudaFuncSetAttribute(gemm_mma<1, false, 256>,  cudaFuncAttributeMaxDynamicSharedMemorySize, G_SMEM);
    cudaFuncSetAttribute(gemm_mma<2, true, 1024>,  cudaFuncAttributeMaxDynamicSharedMemorySize, G_SMEM);

    // 1. merged ln1 + weight prep (independent work, one launch)
    prep_kernel<<<16384 + 3072, 256>>>(feat, ln1_g, ln1_b, p_ln,
                                       w_qkv, w_proj, w1, w2,
                                       p_wqkvT, p_wprojT, p_w1T, p_w2T);
    // 2. fused qkv + attention -> g_attn (bf16, original order)
    fused_qkv_attn<<<P_TILES, 256, FA_SMEM>>>(p_ln, p_wqkvT, b_qkv, order, p_attn);
    // 3. x = feat + attn @ w_proj + b_proj  (f32)
    gemm_mma<2, true, 256><<<dim3(2, N_TOK / 128), 256, G_SMEM>>>(
        p_attn, p_wprojT, b_proj, feat, p_x, C_DIM);
    // 4. ln2(x) -> bf16
    ln_kernel<<<N_TOK / 8, dim3(32, 8)>>>(p_x, ln2_g, ln2_b, p_ln);
    // 5. mid = gelu(ln2 @ w1 + b1)
    gemm_mma<1, false, 256><<<dim3(8, N_TOK / 128), 256, G_SMEM>>>(
        p_ln, p_w1T, b1, nullptr, p_mid, HID_DIM);
    // 6. out = x + mid @ w2 + b2  (f32)
    gemm_mma<2, true, 1024><<<dim3(2, N_TOK / 128), 256, G_SMEM>>>(
        p_mid, p_w2T, b2, p_x, (float*)d_out, C_DIM);
}

// round 14
// speedup vs baseline: 1.0859x; 1.0859x over previous
#include <cuda_runtime.h>
#include <cuda_bf16.h>
#include <math.h>
#include <stdint.h>

#define N_TOK 131072
#define C_DIM 256
#define HID_DIM 1024
#define H_HEADS 8
#define D_HEAD 32
#define K_WIN 128
#define P_TILES (N_TOK / K_WIN)
#define SCALE_ATTN 0.17677669529663687f

typedef __nv_bfloat16 bf16;

// ---------------- scratch (device globals) ----------------
__device__ bf16  g_ln[N_TOK * C_DIM];
__device__ bf16  g_attn[N_TOK * C_DIM];
__device__ float g_x[N_TOK * C_DIM];
__device__ bf16  g_mid[N_TOK * HID_DIM];
__device__ bf16  g_wqkvT[3 * C_DIM * C_DIM];
__device__ bf16  g_wprojT[C_DIM * C_DIM];
__device__ bf16  g_w1T[HID_DIM * C_DIM];
__device__ bf16  g_w2T[C_DIM * HID_DIM];

// ---------------- PTX helpers (plain sm_103-safe) ----------
__device__ __forceinline__ uint32_t smem_u32(const void* p) {
    uint32_t a;
    asm("{ .reg .u64 t; cvta.to.shared.u64 t, %1; cvt.u32.u64 %0, t; }" : "=r"(a) : "l"(p));
    return a;
}
#define CP_ASYNC16(dst, src) \
    asm volatile("cp.async.cg.shared.global [%0], [%1], 16;" :: "r"(dst), "l"(src))
#define CP_COMMIT() asm volatile("cp.async.commit_group;" ::: "memory")
#define CP_WAIT(n)  asm volatile("cp.async.wait_group %0;" :: "n"(n) : "memory")

#define LDMATRIX_X4(r0, r1, r2, r3, addr) \
    asm volatile("ldmatrix.sync.aligned.m8n8.x4.shared.b16 {%0,%1,%2,%3}, [%4];" \
                 : "=r"(r0), "=r"(r1), "=r"(r2), "=r"(r3) : "r"(addr))
#define LDMATRIX_X4_T(r0, r1, r2, r3, addr) \
    asm volatile("ldmatrix.sync.aligned.m8n8.x4.trans.shared.b16 {%0,%1,%2,%3}, [%4];" \
                 : "=r"(r0), "=r"(r1), "=r"(r2), "=r"(r3) : "r"(addr))

#define MMA_BF16(c, a, b0, b1) \
    asm volatile("mma.sync.aligned.m16n8k16.row.col.f32.bf16.bf16.f32 " \
                 "{%0,%1,%2,%3}, {%4,%5,%6,%7}, {%8,%9}, {%0,%1,%2,%3};" \
                 : "+f"((c)[0]), "+f"((c)[1]), "+f"((c)[2]), "+f"((c)[3]) \
                 : "r"((a)[0]), "r"((a)[1]), "r"((a)[2]), "r"((a)[3]), \
                   "r"(b0), "r"(b1))

__device__ __forceinline__ float gelu_tanh(float x) {
    float x3 = x * x * x;
    float t = tanhf(0.7978845608028654f * (x + 0.044715f * x3));
    return 0.5f * x * (1.0f + t);
}
__device__ __forceinline__ uint32_t packbf(float x, float y) {
    __nv_bfloat162 t = __float22bfloat162_rn(make_float2(x, y));
    return *(uint32_t*)&t;
}

// ---------------- merged weight transpose + bf16 convert ----------------
__global__ void wprep_all(const float* __restrict__ wqkv, const float* __restrict__ wproj,
                          const float* __restrict__ w1, const float* __restrict__ w2,
                          bf16* __restrict__ o_qkv, bf16* __restrict__ o_proj,
                          bf16* __restrict__ o_w1, bf16* __restrict__ o_w2) {
    int idx = blockIdx.x * 256 + threadIdx.x;
    if (idx < 196608) {
        int n = idx / 256, k = idx % 256;
        o_qkv[idx] = __float2bfloat16(wqkv[k * 768 + n]);
    } else if (idx < 262144) {
        int i = idx - 196608;
        int n = i / 256, k = i % 256;
        o_proj[i] = __float2bfloat16(wproj[k * 256 + n]);
    } else if (idx < 524288) {
        int i = idx - 262144;
        int n = i / 256, k = i % 256;
        o_w1[i] = __float2bfloat16(w1[k * 1024 + n]);
    } else {
        int i = idx - 524288;
        int n = i / 1024, k = i % 1024;
        o_w2[i] = __float2bfloat16(w2[k * 256 + n]);
    }
}

// ---------------- layernorm f32 -> bf16 ----------------
__global__ void ln_kernel(const float* __restrict__ x, const float* __restrict__ g,
                          const float* __restrict__ b, bf16* __restrict__ y) {
    int row = blockIdx.x * 8 + threadIdx.y;
    int lane = threadIdx.x;
    const float4* xr = (const float4*)(x + (size_t)row * C_DIM);
    float4 v0 = xr[lane * 2];
    float4 v1 = xr[lane * 2 + 1];
    float s = v0.x + v0.y + v0.z + v0.w + v1.x + v1.y + v1.z + v1.w;
    float ss = v0.x*v0.x + v0.y*v0.y + v0.z*v0.z + v0.w*v0.w
             + v1.x*v1.x + v1.y*v1.y + v1.z*v1.z + v1.w*v1.w;
    #pragma unroll
    for (int o = 16; o > 0; o >>= 1) {
        s  += __shfl_xor_sync(0xffffffffu, s,  o);
        ss += __shfl_xor_sync(0xffffffffu, ss, o);
    }
    float mu = s * (1.0f / C_DIM);
    float var = ss * (1.0f / C_DIM) - mu * mu;
    float rstd = rsqrtf(var + 1e-5f);
    const float4* g4 = (const float4*)g;
    const float4* b4 = (const float4*)b;
    float4 ga = g4[lane * 2], gb = g4[lane * 2 + 1];
    float4 ba = b4[lane * 2], bb = b4[lane * 2 + 1];
    float o[8];
    o[0] = (v0.x - mu) * rstd * ga.x + ba.x;
    o[1] = (v0.y - mu) * rstd * ga.y + ba.y;
    o[2] = (v0.z - mu) * rstd * ga.z + ba.z;
    o[3] = (v0.w - mu) * rstd * ga.w + ba.w;
    o[4] = (v1.x - mu) * rstd * gb.x + bb.x;
    o[5] = (v1.y - mu) * rstd * gb.y + bb.y;
    o[6] = (v1.z - mu) * rstd * gb.z + bb.z;
    o[7] = (v1.w - mu) * rstd * gb.w + bb.w;
    uint32_t pk[4];
    #pragma unroll
    for (int i = 0; i < 4; i++) pk[i] = packbf(o[2*i], o[2*i+1]);
    *(uint4*)(y + (size_t)row * C_DIM + lane * 8) = make_uint4(pk[0], pk[1], pk[2], pk[3]);
}

// ---------------- HMMA GEMM (champion): BK=64, 3-stage, runtime K ----------
#define G_LDS 72
#define G_STAGE (2 * 128 * G_LDS)
#define G_SMEM (3 * G_STAGE * 2)

template <int EPI, bool OF32>
__global__ void __launch_bounds__(256, 2)
gemm_mma(const bf16* __restrict__ A, const bf16* __restrict__ BT,
         const float* __restrict__ bias, const float* __restrict__ res,
         void* __restrict__ Cout, int M, int Nn, int Kk) {
    constexpr int BK = 64;
    extern __shared__ bf16 smbuf[];

    const int tid = threadIdx.x;
    const int wid = tid >> 5, lane = tid & 31;
    const int wm = wid & 1, wn = wid >> 1;
    const int row0 = blockIdx.y * 128;
    const int col0 = blockIdx.x * 128;

    float acc[4][4][4];
    #pragma unroll
    for (int mi = 0; mi < 4; mi++)
        #pragma unroll
        for (int ni = 0; ni < 4; ni++)
            #pragma unroll
            for (int e = 0; e < 4; e++) acc[mi][ni][e] = 0.0f;

    auto load_stage = [&](int s, int k0) {
        bf16* As = smbuf + s * G_STAGE;
        bf16* Bs = As + 128 * G_LDS;
        #pragma unroll
        for (int i = 0; i < 4; i++) {
            int idx = tid + i * 256;
            int r = idx >> 3, c = (idx & 7) * 8;
            CP_ASYNC16(smem_u32(As + r * G_LDS + c), A + (size_t)(row0 + r) * Kk + k0 + c);
        }
        #pragma unroll
        for (int i = 0; i < 4; i++) {
            int idx = tid + i * 256;
            int r = idx >> 3, c = (idx & 7) * 8;
            CP_ASYNC16(smem_u32(Bs + r * G_LDS + c), BT + (size_t)(col0 + r) * Kk + k0 + c);
        }
    };

    const int nk = Kk / BK;
    load_stage(0, 0); CP_COMMIT();
    load_stage(1, BK); CP_COMMIT();

    for (int kt = 0; kt < nk; kt++) {
        int s = kt % 3;
        if (kt < nk - 1) CP_WAIT(1); else CP_WAIT(0);
        __syncthreads();
        if (kt + 2 < nk) { load_stage((kt + 2) % 3, (kt + 2) * BK); CP_COMMIT(); }

        bf16* As = smbuf + s * G_STAGE;
        bf16* Bs = As + 128 * G_LDS;
        #pragma unroll
        for (int ks = 0; ks < 4; ks++) {
            const int k0 = ks * 16;
            uint32_t a[4][4];
            #pragma unroll
            for (int mi = 0; mi < 4; mi++) {
                int r = wm * 64 + mi * 16 + (lane & 15);
                int c = k0 + ((lane >> 4) << 3);
                LDMATRIX_X4(a[mi][0], a[mi][1], a[mi][2], a[mi][3],
                            smem_u32(As + r * G_LDS + c));
            }
            uint32_t b[4][2];
            #pragma unroll
            for (int bi = 0; bi < 2; bi++) {
                int r = wn * 32 + bi * 16 + (lane & 15);
                int c = k0 + ((lane >> 4) << 3);
                uint32_t r0, r1, r2, r3;
                LDMATRIX_X4(r0, r1, r2, r3, smem_u32(Bs + r * G_LDS + c));
                b[2*bi][0] = r0; b[2*bi][1] = r2;
                b[2*bi+1][0] = r1; b[2*bi+1][1] = r3;
            }
            #pragma unroll
            for (int mi = 0; mi < 4; mi++)
                #pragma unroll
                for (int ni = 0; ni < 4; ni++)
                    MMA_BF16(acc[mi][ni], a[mi], b[ni][0], b[ni][1]);
        }
    }

    #pragma unroll
    for (int mi = 0; mi < 4; mi++) {
        #pragma unroll
        for (int ni = 0; ni < 4; ni++) {
            int r0 = row0 + wm * 64 + mi * 16 + (lane >> 2);
            int cc = col0 + wn * 32 + ni * 8 + (lane & 3) * 2;
            float2 bv = *(const float2*)(bias + cc);
            #pragma unroll
            for (int half = 0; half < 2; half++) {
                int r = r0 + half * 8;
                float vx = acc[mi][ni][2*half]   + bv.x;
                float vy = acc[mi][ni][2*half+1] + bv.y;
                if (EPI == 1) { vx = gelu_tanh(vx); vy = gelu_tanh(vy); }
                if (EPI == 2) {
                    float2 rv = *(const float2*)(res + (size_t)r * Nn + cc);
                    vx += rv.x; vy += rv.y;
                }
                if (OF32) {
                    *(float2*)((float*)Cout + (size_t)r * Nn + cc) = make_float2(vx, vy);
                } else {
                    *(uint32_t*)((bf16*)Cout + (size_t)r * Nn + cc) = packbf(vx, vy);
                }
            }
        }
    }
}

// ------- K=256 specialization: 4-iter kt loop fully unrolled (small) -------
template <int EPI, bool OF32>
__global__ void __launch_bounds__(256, 2)
gemm_k256(const bf16* __restrict__ A, const bf16* __restrict__ BT,
          const float* __restrict__ bias, const float* __restrict__ res,
          void* __restrict__ Cout, int Nn) {
    constexpr int BK = 64, KK = 256, NK = 4;
    extern __shared__ bf16 smbuf[];

    const int tid = threadIdx.x;
    const int wid = tid >> 5, lane = tid & 31;
    const int wm = wid & 1, wn = wid >> 1;
    const int row0 = blockIdx.y * 128;
    const int col0 = blockIdx.x * 128;

    float acc[4][4][4];
    #pragma unroll
    for (int mi = 0; mi < 4; mi++)
        #pragma unroll
        for (int ni = 0; ni < 4; ni++)
            #pragma unroll
            for (int e = 0; e < 4; e++) acc[mi][ni][e] = 0.0f;

    auto load_stage = [&](int s, int k0) {
        bf16* As = smbuf + s * G_STAGE;
        bf16* Bs = As + 128 * G_LDS;
        #pragma unroll
        for (int i = 0; i < 4; i++) {
            int idx = tid + i * 256;
            int r = idx >> 3, c = (idx & 7) * 8;
            CP_ASYNC16(smem_u32(As + r * G_LDS + c), A + (size_t)(row0 + r) * KK + k0 + c);
        }
        #pragma unroll
        for (int i = 0; i < 4; i++) {
            int idx = tid + i * 256;
            int r = idx >> 3, c = (idx & 7) * 8;
            CP_ASYNC16(smem_u32(Bs + r * G_LDS + c), BT + (size_t)(col0 + r) * KK + k0 + c);
        }
    };

    load_stage(0, 0); CP_COMMIT();
    load_stage(1, BK); CP_COMMIT();

    #pragma unroll
    for (int kt = 0; kt < NK; kt++) {
        if (kt < NK - 1) CP_WAIT(1); else CP_WAIT(0);
        __syncthreads();
        if (kt + 2 < NK) { load_stage((kt + 2) % 3, (kt + 2) * BK); CP_COMMIT(); }

        bf16* As = smbuf + (kt % 3) * G_STAGE;   // compile-time after unroll
        bf16* Bs = As + 128 * G_LDS;
        #pragma unroll
        for (int ks = 0; ks < 4; ks++) {
            const int k0 = ks * 16;
            uint32_t a[4][4];
            #pragma unroll
            for (int mi = 0; mi < 4; mi++) {
                int r = wm * 64 + mi * 16 + (lane & 15);
                int c = k0 + ((lane >> 4) << 3);
                LDMATRIX_X4(a[mi][0], a[mi][1], a[mi][2], a[mi][3],
                            smem_u32(As + r * G_LDS + c));
            }
            uint32_t b[4][2];
            #pragma unroll
            for (int bi = 0; bi < 2; bi++) {
                int r = wn * 32 + bi * 16 + (lane & 15);
                int c = k0 + ((lane >> 4) << 3);
                uint32_t r0, r1, r2, r3;
                LDMATRIX_X4(r0, r1, r2, r3, smem_u32(Bs + r * G_LDS + c));
                b[2*bi][0] = r0; b[2*bi][1] = r2;
                b[2*bi+1][0] = r1; b[2*bi+1][1] = r3;
            }
            #pragma unroll
            for (int mi = 0; mi < 4; mi++)
                #pragma unroll
                for (int ni = 0; ni < 4; ni++)
                    MMA_BF16(acc[mi][ni], a[mi], b[ni][0], b[ni][1]);
        }
    }

    #pragma unroll
    for (int mi = 0; mi < 4; mi++) {
        #pragma unroll
        for (int ni = 0; ni < 4; ni++) {
            int r0 = row0 + wm * 64 + mi * 16 + (lane >> 2);
            int cc = col0 + wn * 32 + ni * 8 + (lane & 3) * 2;
            float2 bv = *(const float2*)(bias + cc);
            #pragma unroll
            for (int half = 0; half < 2; half++) {
                int r = r0 + half * 8;
                float vx = acc[mi][ni][2*half]   + bv.x;
                float vy = acc[mi][ni][2*half+1] + bv.y;
                if (EPI == 1) { vx = gelu_tanh(vx); vy = gelu_tanh(vy); }
                if (EPI == 2) {
                    float2 rv = *(const float2*)(res + (size_t)r * Nn + cc);
                    vx += rv.x; vy += rv.y;
                }
                if (OF32) {
                    *(float2*)((float*)Cout + (size_t)r * Nn + cc) = make_float2(vx, vy);
                } else {
                    *(uint32_t*)((bf16*)Cout + (size_t)r * Nn + cc) = packbf(vx, vy);
                }
            }
        }
    }
}

// ---------------- fused qkv-GEMM + attention (round-7 champion) ------------
#define FA_SMEM 200192

__global__ void __launch_bounds__(256)
fused_qkv_attn(const bf16* __restrict__ lnin, const bf16* __restrict__ wqkvT,
               const float* __restrict__ bqkv, const int* __restrict__ order,
               bf16* __restrict__ out) {
    extern __shared__ char sm[];
    bf16* pA = (bf16*)(sm);
    bf16* pW = (bf16*)(sm + 67584);
    bf16* pQ = (bf16*)(sm + 168960);
    bf16* pK = (bf16*)(sm + 179200);
    bf16* pV = (bf16*)(sm + 189440);
    int*  ptok = (int*)(sm + 199680);

    const int p = blockIdx.x;
    const int tid = threadIdx.x, wid = tid >> 5, lane = tid & 31;
    const int m0 = wid * 16;

    if (tid < 128) ptok[tid] = order[p * K_WIN + tid];

    #pragma unroll
    for (int i = 0; i < 16; i++) {
        int ch = tid + i * 256;
        int r = ch >> 5, c = (ch & 31) * 8;
        int token = order[p * K_WIN + r];
        CP_ASYNC16(smem_u32(pA + r * 264 + c), lnin + (size_t)token * C_DIM + c);
    }
    auto load_w = [&](int s, int h) {
        bf16* dst = pW + s * 25344;
        #pragma unroll
        for (int i = 0; i < 12; i++) {
            int ch = tid + i * 256;
            int r = ch >> 5, c = (ch & 31) * 8;
            int row_g = (r >> 5) * 256 + h * 32 + (r & 31);
            CP_ASYNC16(smem_u32(dst + r * 264 + c), wqkvT + (size_t)row_g * C_DIM + c);
        }
    };
    load_w(0, 0);
    CP_COMMIT();

    for (int h = 0; h < H_HEADS; h++) {
        if (h < H_HEADS - 1) { load_w((h + 1) & 1, h + 1); CP_COMMIT(); }
        if (h < H_HEADS - 1) CP_WAIT(1); else CP_WAIT(0);
        __syncthreads();

        float acc[12][4];
        #pragma unroll
        for (int j = 0; j < 12; j++)
            #pragma unroll
            for (int e = 0; e < 4; e++) acc[j][e] = 0.0f;
        const bf16* Wb = pW + (h & 1) * 25344;
        #pragma unroll
        for (int kk = 0; kk < 16; kk++) {
            const int k0 = kk * 16;
            uint32_t a[4];
            LDMATRIX_X4(a[0], a[1], a[2], a[3],
                        smem_u32(pA + (m0 + (lane & 15)) * 264 + k0 + ((lane >> 4) << 3)));
            #pragma unroll
            for (int nt = 0; nt < 6; nt++) {
                uint32_t r0, r1, r2, r3;
                LDMATRIX_X4(r0, r1, r2, r3,
                            smem_u32(Wb + (nt * 16 + (lane & 15)) * 264 + k0 + ((lane >> 4) << 3)));
                MMA_BF16(acc[2*nt],   a, r0, r2);
                MMA_BF16(acc[2*nt+1], a, r1, r3);
            }
        }
        {
            int rr = m0 + (lane >> 2);
            #pragma unroll
            for (int j = 0; j < 12; j++) {
                int n = j * 8 + (lane & 3) * 2;
                int sel = n >> 5, d = n & 31;
                float2 bv = *(const float2*)(bqkv + sel * 256 + h * 32 + d);
                bf16* dst = (sel == 0) ? pQ : (sel == 1) ? pK : pV;
                *(uint32_t*)(dst + rr * 40 + d)       = packbf(acc[j][0] + bv.x, acc[j][1] + bv.y);
                *(uint32_t*)(dst + (rr + 8) * 40 + d) = packbf(acc[j][2] + bv.x, acc[j][3] + bv.y);
            }
        }
        __syncthreads();

        float sacc[16][4];
        #pragma unroll
        for (int nt = 0; nt < 16; nt++)
            #pragma unroll
            for (int e = 0; e < 4; e++) sacc[nt][e] = 0.0f;
        #pragma unroll
        for (int ksx = 0; ksx < 2; ksx++) {
            const int k0 = ksx * 16;
            uint32_t a[4];
            LDMATRIX_X4(a[0], a[1], a[2], a[3],
                        smem_u32(pQ + (m0 + (lane & 15)) * 40 + k0 + ((lane >> 4) << 3)));
            #pragma unroll
            for (int t = 0; t < 8; t++) {
                uint32_t r0, r1, r2, r3;
                LDMATRIX_X4(r0, r1, r2, r3,
                            smem_u32(pK + (t * 16 + (lane & 15)) * 40 + k0 + ((lane >> 4) << 3)));
                MMA_BF16(sacc[2*t],   a, r0, r2);
                MMA_BF16(sacc[2*t+1], a, r1, r3);
            }
        }

        float m_lo = -INFINITY, m_hi = -INFINITY;
        #pragma unroll
        for (int nt = 0; nt < 16; nt++) {
            #pragma unroll
            for (int e = 0; e < 4; e++) sacc[nt][e] *= SCALE_ATTN;
            m_lo = fmaxf(m_lo, fmaxf(sacc[nt][0], sacc[nt][1]));
            m_hi = fmaxf(m_hi, fmaxf(sacc[nt][2], sacc[nt][3]));
        }
        m_lo = fmaxf(m_lo, __shfl_xor_sync(0xffffffffu, m_lo, 1));
        m_lo = fmaxf(m_lo, __shfl_xor_sync(0xffffffffu, m_lo, 2));
        m_hi = fmaxf(m_hi, __shfl_xor_sync(0xffffffffu, m_hi, 1));
        m_hi = fmaxf(m_hi, __shfl_xor_sync(0xffffffffu, m_hi, 2));

        float l_lo = 0.0f, l_hi = 0.0f;
        uint32_t pf[16][2];
        #pragma unroll
        for (int nt = 0; nt < 16; nt++) {
            float e0 = __expf(sacc[nt][0] - m_lo);
            float e1 = __expf(sacc[nt][1] - m_lo);
            float e2 = __expf(sacc[nt][2] - m_hi);
            float e3 = __expf(sacc[nt][3] - m_hi);
            l_lo += e0 + e1;
            l_hi += e2 + e3;
            pf[nt][0] = packbf(e0, e1);
            pf[nt][1] = packbf(e2, e3);
        }
        l_lo += __shfl_xor_sync(0xffffffffu, l_lo, 1);
        l_lo += __shfl_xor_sync(0xffffffffu, l_lo, 2);
        l_hi += __shfl_xor_sync(0xffffffffu, l_hi, 1);
        l_hi += __shfl_xor_sync(0xffffffffu, l_hi, 2);

        float acco[4][4];
        #pragma unroll
        for (int nt = 0; nt < 4; nt++)
            #pragma unroll
            for (int e = 0; e < 4; e++) acco[nt][e] = 0.0f;
        #pragma unroll
        for (int kk = 0; kk < 8; kk++) {
            uint32_t a[4] = {pf[2*kk][0], pf[2*kk][1], pf[2*kk+1][0], pf[2*kk+1][1]};
            uint32_t r0, r1, r2, r3;
            LDMATRIX_X4_T(r0, r1, r2, r3,
                          smem_u32(pV + (kk * 16 + (lane & 15)) * 40 + ((lane >> 4) << 3)));
            MMA_BF16(acco[0], a, r0, r1);
            MMA_BF16(acco[1], a, r2, r3);
            uint32_t s0, s1, s2, s3;
            LDMATRIX_X4_T(s0, s1, s2, s3,
                          smem_u32(pV + (kk * 16 + (lane & 15)) * 40 + 16 + ((lane >> 4) << 3)));
            MMA_BF16(acco[2], a, s0, s1);
            MMA_BF16(acco[3], a, s2, s3);
        }

        float inv_lo = 1.0f / l_lo, inv_hi = 1.0f / l_hi;
        int r_lo = m0 + (lane >> 2);
        int tok_lo = ptok[r_lo], tok_hi = ptok[r_lo + 8];
        bf16* o_lo = out + (size_t)tok_lo * C_DIM + h * D_HEAD + (lane & 3) * 2;
        bf16* o_hi = out + (size_t)tok_hi * C_DIM + h * D_HEAD + (lane & 3) * 2;
        #pragma unroll
        for (int nt = 0; nt < 4; nt++) {
            *(uint32_t*)(o_lo + nt * 8) = packbf(acco[nt][0] * inv_lo, acco[nt][1] * inv_lo);
            *(uint32_t*)(o_hi + nt * 8) = packbf(acco[nt][2] * inv_hi, acco[nt][3] * inv_hi);
        }
    }
}

// ---------------------------- launch ---------------------------------------
extern "C" void kernel_launch(void* const* d_in, const int* in_sizes, int n_in,
                              void* d_out, int out_size) {
    const float* feat   = (const float*)d_in[0];
    const float* ln1_g  = (const float*)d_in[1];
    const float* ln1_b  = (const float*)d_in[2];
    const float* w_qkv  = (const float*)d_in[3];
    const float* b_qkv  = (const float*)d_in[4];
    const float* w_proj = (const float*)d_in[5];
    const float* b_proj = (const float*)d_in[6];
    const float* ln2_g  = (const float*)d_in[7];
    const float* ln2_b  = (const float*)d_in[8];
    const float* w1     = (const float*)d_in[9];
    const float* b1     = (const float*)d_in[10];
    const float* w2     = (const float*)d_in[11];
    const float* b2     = (const float*)d_in[12];
    const int*   order  = (const int*)d_in[13];

    bf16 *p_ln, *p_attn, *p_mid, *p_wqkvT, *p_wprojT, *p_w1T, *p_w2T;
    float* p_x;
    cudaGetSymbolAddress((void**)&p_ln,     g_ln);
    cudaGetSymbolAddress((void**)&p_attn,   g_attn);
    cudaGetSymbolAddress((void**)&p_x,      g_x);
    cudaGetSymbolAddress((void**)&p_mid,    g_mid);
    cudaGetSymbolAddress((void**)&p_wqkvT,  g_wqkvT);
    cudaGetSymbolAddress((void**)&p_wprojT, g_wprojT);
    cudaGetSymbolAddress((void**)&p_w1T,    g_w1T);
    cudaGetSymbolAddress((void**)&p_w2T,    g_w2T);

    cudaFuncSetAttribute(fused_qkv_attn, cudaFuncAttributeMaxDynamicSharedMemorySize, FA_SMEM);
    cudaFuncSetAttribute(gemm_k256<2, true>,  cudaFuncAttributeMaxDynamicSharedMemorySize, G_SMEM);
    cudaFuncSetAttribute(gemm_k256<1, false>, cudaFuncAttributeMaxDynamicSharedMemorySize, G_SMEM);
    cudaFuncSetAttribute(gemm_mma<2, true>,   cudaFuncAttributeMaxDynamicSharedMemorySize, G_SMEM);

    // 1. weight transpose + bf16 (single launch)
    wprep_all<<<3072, 256>>>(w_qkv, w_proj, w1, w2, p_wqkvT, p_wprojT, p_w1T, p_w2T);

    dim3 lnBlk(32, 8);
    // 2. ln1(feat) -> bf16
    ln_kernel<<<N_TOK / 8, lnBlk>>>(feat, ln1_g, ln1_b, p_ln);
    // 3. fused qkv + attention -> g_attn (bf16, original order)
    fused_qkv_attn<<<P_TILES, 256, FA_SMEM>>>(p_ln, p_wqkvT, b_qkv, order, p_attn);
    // 4. x = feat + attn @ w_proj + b_proj  (f32)  — unrolled K=256
    gemm_k256<2, true><<<dim3(2, N_TOK / 128), 256, G_SMEM>>>(
        p_attn, p_wprojT, b_proj, feat, p_x, C_DIM);
    // 5. ln2(x) -> bf16
    ln_kernel<<<N_TOK / 8, lnBlk>>>(p_x, ln2_g, ln2_b, p_ln);
    // 6. mid = gelu(ln2 @ w1 + b1)  — unrolled K=256
    gemm_k256<1, false><<<dim3(8, N_TOK / 128), 256, G_SMEM>>>(
        p_ln, p_w1T, b1, nullptr, p_mid, HID_DIM);
    // 7. out = x + mid @ w2 + b2  (f32) — champion runtime-K kernel
    gemm_mma<2, true><<<dim3(2, N_TOK / 128), 256, G_SMEM>>>(
        p_mid, p_w2T, b2, p_x, (float*)d_out, N_TOK, C_DIM, HID_DIM);
}

// round 15
// speedup vs baseline: 1.1075x; 1.0199x over previous
#include <cuda_runtime.h>
#include <cuda_bf16.h>
#include <math.h>
#include <stdint.h>

#define N_TOK 131072
#define C_DIM 256
#define HID_DIM 1024
#define H_HEADS 8
#define D_HEAD 32
#define K_WIN 128
#define P_TILES (N_TOK / K_WIN)
#define SCALE_ATTN 0.17677669529663687f

typedef __nv_bfloat16 bf16;

// ---------------- scratch (device globals) ----------------
__device__ bf16  g_ln[N_TOK * C_DIM];
__device__ bf16  g_attn[N_TOK * C_DIM];
__device__ float g_x[N_TOK * C_DIM];
__device__ bf16  g_mid[N_TOK * HID_DIM];
__device__ bf16  g_wqkvT[3 * C_DIM * C_DIM];
__device__ bf16  g_wprojT[C_DIM * C_DIM];
__device__ bf16  g_w1T[HID_DIM * C_DIM];
__device__ bf16  g_w2T[C_DIM * HID_DIM];

// ---------------- PTX helpers (plain sm_103-safe) ----------
__device__ __forceinline__ uint32_t smem_u32(const void* p) {
    uint32_t a;
    asm("{ .reg .u64 t; cvta.to.shared.u64 t, %1; cvt.u32.u64 %0, t; }" : "=r"(a) : "l"(p));
    return a;
}
#define CP_ASYNC16(dst, src) \
    asm volatile("cp.async.cg.shared.global [%0], [%1], 16;" :: "r"(dst), "l"(src))
#define CP_COMMIT() asm volatile("cp.async.commit_group;" ::: "memory")
#define CP_WAIT(n)  asm volatile("cp.async.wait_group %0;" :: "n"(n) : "memory")

#define LDMATRIX_X4(r0, r1, r2, r3, addr) \
    asm volatile("ldmatrix.sync.aligned.m8n8.x4.shared.b16 {%0,%1,%2,%3}, [%4];" \
                 : "=r"(r0), "=r"(r1), "=r"(r2), "=r"(r3) : "r"(addr))
#define LDMATRIX_X4_T(r0, r1, r2, r3, addr) \
    asm volatile("ldmatrix.sync.aligned.m8n8.x4.trans.shared.b16 {%0,%1,%2,%3}, [%4];" \
                 : "=r"(r0), "=r"(r1), "=r"(r2), "=r"(r3) : "r"(addr))

#define MMA_BF16(c, a, b0, b1) \
    asm volatile("mma.sync.aligned.m16n8k16.row.col.f32.bf16.bf16.f32 " \
                 "{%0,%1,%2,%3}, {%4,%5,%6,%7}, {%8,%9}, {%0,%1,%2,%3};" \
                 : "+f"((c)[0]), "+f"((c)[1]), "+f"((c)[2]), "+f"((c)[3]) \
                 : "r"((a)[0]), "r"((a)[1]), "r"((a)[2]), "r"((a)[3]), \
                   "r"(b0), "r"(b1))

__device__ __forceinline__ float gelu_tanh(float x) {
    float x3 = x * x * x;
    float t = tanhf(0.7978845608028654f * (x + 0.044715f * x3));
    return 0.5f * x * (1.0f + t);
}
__device__ __forceinline__ uint32_t packbf(float x, float y) {
    __nv_bfloat162 t = __float22bfloat162_rn(make_float2(x, y));
    return *(uint32_t*)&t;
}

// ---------- merged prep: ln1 (blocks 0..16383) + weight prep (rest) --------
__global__ void prep_kernel(const float* __restrict__ x, const float* __restrict__ g,
                            const float* __restrict__ b, bf16* __restrict__ y,
                            const float* __restrict__ wqkv, const float* __restrict__ wproj,
                            const float* __restrict__ w1, const float* __restrict__ w2,
                            bf16* __restrict__ o_qkv, bf16* __restrict__ o_proj,
                            bf16* __restrict__ o_w1, bf16* __restrict__ o_w2) {
    if (blockIdx.x < 16384) {
        int row = blockIdx.x * 8 + (threadIdx.x >> 5);
        int lane = threadIdx.x & 31;
        const float4* xr = (const float4*)(x + (size_t)row * C_DIM);
        float4 v0 = xr[lane * 2];
        float4 v1 = xr[lane * 2 + 1];
        float s = v0.x + v0.y + v0.z + v0.w + v1.x + v1.y + v1.z + v1.w;
        float ss = v0.x*v0.x + v0.y*v0.y + v0.z*v0.z + v0.w*v0.w
                 + v1.x*v1.x + v1.y*v1.y + v1.z*v1.z + v1.w*v1.w;
        #pragma unroll
        for (int o = 16; o > 0; o >>= 1) {
            s  += __shfl_xor_sync(0xffffffffu, s,  o);
            ss += __shfl_xor_sync(0xffffffffu, ss, o);
        }
        float mu = s * (1.0f / C_DIM);
        float var = ss * (1.0f / C_DIM) - mu * mu;
        float rstd = rsqrtf(var + 1e-5f);
        const float4* g4 = (const float4*)g;
        const float4* b4 = (const float4*)b;
        float4 ga = g4[lane * 2], gb = g4[lane * 2 + 1];
        float4 ba = b4[lane * 2], bb = b4[lane * 2 + 1];
        float o[8];
        o[0] = (v0.x - mu) * rstd * ga.x + ba.x;
        o[1] = (v0.y - mu) * rstd * ga.y + ba.y;
        o[2] = (v0.z - mu) * rstd * ga.z + ba.z;
        o[3] = (v0.w - mu) * rstd * ga.w + ba.w;
        o[4] = (v1.x - mu) * rstd * gb.x + bb.x;
        o[5] = (v1.y - mu) * rstd * gb.y + bb.y;
        o[6] = (v1.z - mu) * rstd * gb.z + bb.z;
        o[7] = (v1.w - mu) * rstd * gb.w + bb.w;
        uint32_t pk[4];
        #pragma unroll
        for (int i = 0; i < 4; i++) pk[i] = packbf(o[2*i], o[2*i+1]);
        *(uint4*)(y + (size_t)row * C_DIM + lane * 8) = make_uint4(pk[0], pk[1], pk[2], pk[3]);
    } else {
        int idx = (blockIdx.x - 16384) * 256 + threadIdx.x;
        if (idx < 196608) {
            int n = idx / 256, k = idx % 256;
            o_qkv[idx] = __float2bfloat16(wqkv[k * 768 + n]);
        } else if (idx < 262144) {
            int i = idx - 196608;
            int n = i / 256, k = i % 256;
            o_proj[i] = __float2bfloat16(wproj[k * 256 + n]);
        } else if (idx < 524288) {
            int i = idx - 262144;
            int n = i / 256, k = i % 256;
            o_w1[i] = __float2bfloat16(w1[k * 1024 + n]);
        } else {
            int i = idx - 524288;
            int n = i / 1024, k = i % 1024;
            o_w2[i] = __float2bfloat16(w2[k * 256 + n]);
        }
    }
}

// ---------------- layernorm f32 -> bf16 (ln2) ----------------
__global__ void ln_kernel(const float* __restrict__ x, const float* __restrict__ g,
                          const float* __restrict__ b, bf16* __restrict__ y) {
    int row = blockIdx.x * 8 + threadIdx.y;
    int lane = threadIdx.x;
    const float4* xr = (const float4*)(x + (size_t)row * C_DIM);
    float4 v0 = xr[lane * 2];
    float4 v1 = xr[lane * 2 + 1];
    float s = v0.x + v0.y + v0.z + v0.w + v1.x + v1.y + v1.z + v1.w;
    float ss = v0.x*v0.x + v0.y*v0.y + v0.z*v0.z + v0.w*v0.w
             + v1.x*v1.x + v1.y*v1.y + v1.z*v1.z + v1.w*v1.w;
    #pragma unroll
    for (int o = 16; o > 0; o >>= 1) {
        s  += __shfl_xor_sync(0xffffffffu, s,  o);
        ss += __shfl_xor_sync(0xffffffffu, ss, o);
    }
    float mu = s * (1.0f / C_DIM);
    float var = ss * (1.0f / C_DIM) - mu * mu;
    float rstd = rsqrtf(var + 1e-5f);
    const float4* g4 = (const float4*)g;
    const float4* b4 = (const float4*)b;
    float4 ga = g4[lane * 2], gb = g4[lane * 2 + 1];
    float4 ba = b4[lane * 2], bb = b4[lane * 2 + 1];
    float o[8];
    o[0] = (v0.x - mu) * rstd * ga.x + ba.x;
    o[1] = (v0.y - mu) * rstd * ga.y + ba.y;
    o[2] = (v0.z - mu) * rstd * ga.z + ba.z;
    o[3] = (v0.w - mu) * rstd * ga.w + ba.w;
    o[4] = (v1.x - mu) * rstd * gb.x + bb.x;
    o[5] = (v1.y - mu) * rstd * gb.y + bb.y;
    o[6] = (v1.z - mu) * rstd * gb.z + bb.z;
    o[7] = (v1.w - mu) * rstd * gb.w + bb.w;
    uint32_t pk[4];
    #pragma unroll
    for (int i = 0; i < 4; i++) pk[i] = packbf(o[2*i], o[2*i+1]);
    *(uint4*)(y + (size_t)row * C_DIM + lane * 8) = make_uint4(pk[0], pk[1], pk[2], pk[3]);
}

// ---------------- HMMA GEMM (champion): BK=64, 3-stage, runtime K ----------
#define G_LDS 72
#define G_STAGE (2 * 128 * G_LDS)
#define G_SMEM (3 * G_STAGE * 2)

template <int EPI, bool OF32>
__global__ void __launch_bounds__(256, 2)
gemm_mma(const bf16* __restrict__ A, const bf16* __restrict__ BT,
         const float* __restrict__ bias, const float* __restrict__ res,
         void* __restrict__ Cout, int M, int Nn, int Kk) {
    constexpr int BK = 64;
    extern __shared__ bf16 smbuf[];

    const int tid = threadIdx.x;
    const int wid = tid >> 5, lane = tid & 31;
    const int wm = wid & 1, wn = wid >> 1;
    const int row0 = blockIdx.y * 128;
    const int col0 = blockIdx.x * 128;

    float acc[4][4][4];
    #pragma unroll
    for (int mi = 0; mi < 4; mi++)
        #pragma unroll
        for (int ni = 0; ni < 4; ni++)
            #pragma unroll
            for (int e = 0; e < 4; e++) acc[mi][ni][e] = 0.0f;

    auto load_stage = [&](int s, int k0) {
        bf16* As = smbuf + s * G_STAGE;
        bf16* Bs = As + 128 * G_LDS;
        #pragma unroll
        for (int i = 0; i < 4; i++) {
            int idx = tid + i * 256;
            int r = idx >> 3, c = (idx & 7) * 8;
            CP_ASYNC16(smem_u32(As + r * G_LDS + c), A + (size_t)(row0 + r) * Kk + k0 + c);
        }
        #pragma unroll
        for (int i = 0; i < 4; i++) {
            int idx = tid + i * 256;
            int r = idx >> 3, c = (idx & 7) * 8;
            CP_ASYNC16(smem_u32(Bs + r * G_LDS + c), BT + (size_t)(col0 + r) * Kk + k0 + c);
        }
    };

    const int nk = Kk / BK;
    load_stage(0, 0); CP_COMMIT();
    load_stage(1, BK); CP_COMMIT();

    for (int kt = 0; kt < nk; kt++) {
        int s = kt % 3;
        if (kt < nk - 1) CP_WAIT(1); else CP_WAIT(0);
        __syncthreads();
        if (kt + 2 < nk) { load_stage((kt + 2) % 3, (kt + 2) * BK); CP_COMMIT(); }

        bf16* As = smbuf + s * G_STAGE;
        bf16* Bs = As + 128 * G_LDS;
        #pragma unroll
        for (int ks = 0; ks < 4; ks++) {
            const int k0 = ks * 16;
            uint32_t a[4][4];
            #pragma unroll
            for (int mi = 0; mi < 4; mi++) {
                int r = wm * 64 + mi * 16 + (lane & 15);
                int c = k0 + ((lane >> 4) << 3);
                LDMATRIX_X4(a[mi][0], a[mi][1], a[mi][2], a[mi][3],
                            smem_u32(As + r * G_LDS + c));
            }
            uint32_t b[4][2];
            #pragma unroll
            for (int bi = 0; bi < 2; bi++) {
                int r = wn * 32 + bi * 16 + (lane & 15);
                int c = k0 + ((lane >> 4) << 3);
                uint32_t r0, r1, r2, r3;
                LDMATRIX_X4(r0, r1, r2, r3, smem_u32(Bs + r * G_LDS + c));
                b[2*bi][0] = r0; b[2*bi][1] = r2;
                b[2*bi+1][0] = r1; b[2*bi+1][1] = r3;
            }
            #pragma unroll
            for (int mi = 0; mi < 4; mi++)
                #pragma unroll
                for (int ni = 0; ni < 4; ni++)
                    MMA_BF16(acc[mi][ni], a[mi], b[ni][0], b[ni][1]);
        }
    }

    #pragma unroll
    for (int mi = 0; mi < 4; mi++) {
        #pragma unroll
        for (int ni = 0; ni < 4; ni++) {
            int r0 = row0 + wm * 64 + mi * 16 + (lane >> 2);
            int cc = col0 + wn * 32 + ni * 8 + (lane & 3) * 2;
            float2 bv = *(const float2*)(bias + cc);
            #pragma unroll
            for (int half = 0; half < 2; half++) {
                int r = r0 + half * 8;
                float vx = acc[mi][ni][2*half]   + bv.x;
                float vy = acc[mi][ni][2*half+1] + bv.y;
                if (EPI == 1) { vx = gelu_tanh(vx); vy = gelu_tanh(vy); }
                if (EPI == 2) {
                    float2 rv = *(const float2*)(res + (size_t)r * Nn + cc);
                    vx += rv.x; vy += rv.y;
                }
                if (OF32) {
                    *(float2*)((float*)Cout + (size_t)r * Nn + cc) = make_float2(vx, vy);
                } else {
                    *(uint32_t*)((bf16*)Cout + (size_t)r * Nn + cc) = packbf(vx, vy);
                }
            }
        }
    }
}

// ---------------- fused qkv-GEMM + attention (round-7 champion) ------------
#define FA_SMEM 200192

__global__ void __launch_bounds__(256)
fused_qkv_attn(const bf16* __restrict__ lnin, const bf16* __restrict__ wqkvT,
               const float* __restrict__ bqkv, const int* __restrict__ order,
               bf16* __restrict__ out) {
    extern __shared__ char sm[];
    bf16* pA = (bf16*)(sm);
    bf16* pW = (bf16*)(sm + 67584);
    bf16* pQ = (bf16*)(sm + 168960);
    bf16* pK = (bf16*)(sm + 179200);
    bf16* pV = (bf16*)(sm + 189440);
    int*  ptok = (int*)(sm + 199680);

    const int p = blockIdx.x;
    const int tid = threadIdx.x, wid = tid >> 5, lane = tid & 31;
    const int m0 = wid * 16;

    if (tid < 128) ptok[tid] = order[p * K_WIN + tid];

    #pragma unroll
    for (int i = 0; i < 16; i++) {
        int ch = tid + i * 256;
        int r = ch >> 5, c = (ch & 31) * 8;
        int token = order[p * K_WIN + r];
        CP_ASYNC16(smem_u32(pA + r * 264 + c), lnin + (size_t)token * C_DIM + c);
    }
    auto load_w = [&](int s, int h) {
        bf16* dst = pW + s * 25344;
        #pragma unroll
        for (int i = 0; i < 12; i++) {
            int ch = tid + i * 256;
            int r = ch >> 5, c = (ch & 31) * 8;
            int row_g = (r >> 5) * 256 + h * 32 + (r & 31);
            CP_ASYNC16(smem_u32(dst + r * 264 + c), wqkvT + (size_t)row_g * C_DIM + c);
        }
    };
    load_w(0, 0);
    CP_COMMIT();

    for (int h = 0; h < H_HEADS; h++) {
        if (h < H_HEADS - 1) { load_w((h + 1) & 1, h + 1); CP_COMMIT(); }
        if (h < H_HEADS - 1) CP_WAIT(1); else CP_WAIT(0);
        __syncthreads();

        float acc[12][4];
        #pragma unroll
        for (int j = 0; j < 12; j++)
            #pragma unroll
            for (int e = 0; e < 4; e++) acc[j][e] = 0.0f;
        const bf16* Wb = pW + (h & 1) * 25344;
        #pragma unroll
        for (int kk = 0; kk < 16; kk++) {
            const int k0 = kk * 16;
            uint32_t a[4];
            LDMATRIX_X4(a[0], a[1], a[2], a[3],
                        smem_u32(pA + (m0 + (lane & 15)) * 264 + k0 + ((lane >> 4) << 3)));
            #pragma unroll
            for (int nt = 0; nt < 6; nt++) {
                uint32_t r0, r1, r2, r3;
                LDMATRIX_X4(r0, r1, r2, r3,
                            smem_u32(Wb + (nt * 16 + (lane & 15)) * 264 + k0 + ((lane >> 4) << 3)));
                MMA_BF16(acc[2*nt],   a, r0, r2);
                MMA_BF16(acc[2*nt+1], a, r1, r3);
            }
        }
        {
            int rr = m0 + (lane >> 2);
            #pragma unroll
            for (int j = 0; j < 12; j++) {
                int n = j * 8 + (lane & 3) * 2;
                int sel = n >> 5, d = n & 31;
                float2 bv = *(const float2*)(bqkv + sel * 256 + h * 32 + d);
                bf16* dst = (sel == 0) ? pQ : (sel == 1) ? pK : pV;
                *(uint32_t*)(dst + rr * 40 + d)       = packbf(acc[j][0] + bv.x, acc[j][1] + bv.y);
                *(uint32_t*)(dst + (rr + 8) * 40 + d) = packbf(acc[j][2] + bv.x, acc[j][3] + bv.y);
            }
        }
        __syncthreads();

        float sacc[16][4];
        #pragma unroll
        for (int nt = 0; nt < 16; nt++)
            #pragma unroll
            for (int e = 0; e < 4; e++) sacc[nt][e] = 0.0f;
        #pragma unroll
        for (int ksx = 0; ksx < 2; ksx++) {
            const int k0 = ksx * 16;
            uint32_t a[4];
            LDMATRIX_X4(a[0], a[1], a[2], a[3],
                        smem_u32(pQ + (m0 + (lane & 15)) * 40 + k0 + ((lane >> 4) << 3)));
            #pragma unroll
            for (int t = 0; t < 8; t++) {
                uint32_t r0, r1, r2, r3;
                LDMATRIX_X4(r0, r1, r2, r3,
                            smem_u32(pK + (t * 16 + (lane & 15)) * 40 + k0 + ((lane >> 4) << 3)));
                MMA_BF16(sacc[2*t],   a, r0, r2);
                MMA_BF16(sacc[2*t+1], a, r1, r3);
            }
        }

        float m_lo = -INFINITY, m_hi = -INFINITY;
        #pragma unroll
        for (int nt = 0; nt < 16; nt++) {
            #pragma unroll
            for (int e = 0; e < 4; e++) sacc[nt][e] *= SCALE_ATTN;
            m_lo = fmaxf(m_lo, fmaxf(sacc[nt][0], sacc[nt][1]));
            m_hi = fmaxf(m_hi, fmaxf(sacc[nt][2], sacc[nt][3]));
        }
        m_lo = fmaxf(m_lo, __shfl_xor_sync(0xffffffffu, m_lo, 1));
        m_lo = fmaxf(m_lo, __shfl_xor_sync(0xffffffffu, m_lo, 2));
        m_hi = fmaxf(m_hi, __shfl_xor_sync(0xffffffffu, m_hi, 1));
        m_hi = fmaxf(m_hi, __shfl_xor_sync(0xffffffffu, m_hi, 2));

        float l_lo = 0.0f, l_hi = 0.0f;
        uint32_t pf[16][2];
        #pragma unroll
        for (int nt = 0; nt < 16; nt++) {
            float e0 = __expf(sacc[nt][0] - m_lo);
            float e1 = __expf(sacc[nt][1] - m_lo);
            float e2 = __expf(sacc[nt][2] - m_hi);
            float e3 = __expf(sacc[nt][3] - m_hi);
            l_lo += e0 + e1;
            l_hi += e2 + e3;
            pf[nt][0] = packbf(e0, e1);
            pf[nt][1] = packbf(e2, e3);
        }
        l_lo += __shfl_xor_sync(0xffffffffu, l_lo, 1);
        l_lo += __shfl_xor_sync(0xffffffffu, l_lo, 2);
        l_hi += __shfl_xor_sync(0xffffffffu, l_hi, 1);
        l_hi += __shfl_xor_sync(0xffffffffu, l_hi, 2);

        float acco[4][4];
        #pragma unroll
        for (int nt = 0; nt < 4; nt++)
            #pragma unroll
            for (int e = 0; e < 4; e++) acco[nt][e] = 0.0f;
        #pragma unroll
        for (int kk = 0; kk < 8; kk++) {
            uint32_t a[4] = {pf[2*kk][0], pf[2*kk][1], pf[2*kk+1][0], pf[2*kk+1][1]};
            uint32_t r0, r1, r2, r3;
            LDMATRIX_X4_T(r0, r1, r2, r3,
                          smem_u32(pV + (kk * 16 + (lane & 15)) * 40 + ((lane >> 4) << 3)));
            MMA_BF16(acco[0], a, r0, r1);
            MMA_BF16(acco[1], a, r2, r3);
            uint32_t s0, s1, s2, s3;
            LDMATRIX_X4_T(s0, s1, s2, s3,
                          smem_u32(pV + (kk * 16 + (lane & 15)) * 40 + 16 + ((lane >> 4) << 3)));
            MMA_BF16(acco[2], a, s0, s1);
            MMA_BF16(acco[3], a, s2, s3);
        }

        float inv_lo = 1.0f / l_lo, inv_hi = 1.0f / l_hi;
        int r_lo = m0 + (lane >> 2);
        int tok_lo = ptok[r_lo], tok_hi = ptok[r_lo + 8];
        bf16* o_lo = out + (size_t)tok_lo * C_DIM + h * D_HEAD + (lane & 3) * 2;
        bf16* o_hi = out + (size_t)tok_hi * C_DIM + h * D_HEAD + (lane & 3) * 2;
        #pragma unroll
        for (int nt = 0; nt < 4; nt++) {
            *(uint32_t*)(o_lo + nt * 8) = packbf(acco[nt][0] * inv_lo, acco[nt][1] * inv_lo);
            *(uint32_t*)(o_hi + nt * 8) = packbf(acco[nt][2] * inv_hi, acco[nt][3] * inv_hi);
        }
    }
}

// ---------------------------- launch ---------------------------------------
extern "C" void kernel_launch(void* const* d_in, const int* in_sizes, int n_in,
                              void* d_out, int out_size) {
    const float* feat   = (const float*)d_in[0];
    const float* ln1_g  = (const float*)d_in[1];
    const float* ln1_b  = (const float*)d_in[2];
    const float* w_qkv  = (const float*)d_in[3];
    const float* b_qkv  = (const float*)d_in[4];
    const float* w_proj = (const float*)d_in[5];
    const float* b_proj = (const float*)d_in[6];
    const float* ln2_g  = (const float*)d_in[7];
    const float* ln2_b  = (const float*)d_in[8];
    const float* w1     = (const float*)d_in[9];
    const float* b1     = (const float*)d_in[10];
    const float* w2     = (const float*)d_in[11];
    const float* b2     = (const float*)d_in[12];
    const int*   order  = (const int*)d_in[13];

    bf16 *p_ln, *p_attn, *p_mid, *p_wqkvT, *p_wprojT, *p_w1T, *p_w2T;
    float* p_x;
    cudaGetSymbolAddress((void**)&p_ln,     g_ln);
    cudaGetSymbolAddress((void**)&p_attn,   g_attn);
    cudaGetSymbolAddress((void**)&p_x,      g_x);
    cudaGetSymbolAddress((void**)&p_mid,    g_mid);
    cudaGetSymbolAddress((void**)&p_wqkvT,  g_wqkvT);
    cudaGetSymbolAddress((void**)&p_wprojT, g_wprojT);
    cudaGetSymbolAddress((void**)&p_w1T,    g_w1T);
    cudaGetSymbolAddress((void**)&p_w2T,    g_w2T);

    cudaFuncSetAttribute(fused_qkv_attn, cudaFuncAttributeMaxDynamicSharedMemorySize, FA_SMEM);
    cudaFuncSetAttribute(gemm_mma<2, true>,  cudaFuncAttributeMaxDynamicSharedMemorySize, G_SMEM);
    cudaFuncSetAttribute(gemm_mma<1, false>, cudaFuncAttributeMaxDynamicSharedMemorySize, G_SMEM);

    // 1. merged ln1 + weight prep (independent work, one launch)
    prep_kernel<<<16384 + 3072, 256>>>(feat, ln1_g, ln1_b, p_ln,
                                       w_qkv, w_proj, w1, w2,
                                       p_wqkvT, p_wprojT, p_w1T, p_w2T);
    // 2. fused qkv + attention -> g_attn (bf16, original order)
    fused_qkv_attn<<<P_TILES, 256, FA_SMEM>>>(p_ln, p_wqkvT, b_qkv, order, p_attn);
    // 3. x = feat + attn @ w_proj + b_proj  (f32)
    gemm_mma<2, true><<<dim3(2, N_TOK / 128), 256, G_SMEM>>>(
        p_attn, p_wprojT, b_proj, feat, p_x, N_TOK, C_DIM, C_DIM);
    // 4. ln2(x) -> bf16
    ln_kernel<<<N_TOK / 8, dim3(32, 8)>>>(p_x, ln2_g, ln2_b, p_ln);
    // 5. mid = gelu(ln2 @ w1 + b1)
    gemm_mma<1, false><<<dim3(8, N_TOK / 128), 256, G_SMEM>>>(
        p_ln, p_w1T, b1, nullptr, p_mid, N_TOK, HID_DIM, C_DIM);
    // 6. out = x + mid @ w2 + b2  (f32)
    gemm_mma<2, true><<<dim3(2, N_TOK / 128), 256, G_SMEM>>>(
        p_mid, p_w2T, b2, p_x, (float*)d_out, N_TOK, C_DIM, HID_DIM);
}

// round 16
// speedup vs baseline: 1.1078x; 1.0003x over previous
#include <cuda_runtime.h>
#include <cuda_bf16.h>
#include <math.h>
#include <stdint.h>

#define N_TOK 131072
#define C_DIM 256
#define HID_DIM 1024
#define H_HEADS 8
#define D_HEAD 32
#define K_WIN 128
#define P_TILES (N_TOK / K_WIN)
#define SCALE_ATTN 0.17677669529663687f

typedef __nv_bfloat16 bf16;

// ---------------- scratch (device globals) ----------------
__device__ bf16  g_ln[N_TOK * C_DIM];
__device__ bf16  g_attn[N_TOK * C_DIM];
__device__ float g_x[N_TOK * C_DIM];
__device__ bf16  g_mid[N_TOK * HID_DIM];
__device__ bf16  g_wqkvT[3 * C_DIM * C_DIM];
__device__ bf16  g_wprojT[C_DIM * C_DIM];
__device__ bf16  g_w1T[HID_DIM * C_DIM];
__device__ bf16  g_w2T[C_DIM * HID_DIM];
__device__ float2 g_rowpart[N_TOK * 8];      // 8 deterministic slots per row
__device__ int    g_cnt[N_TOK / 128];        // per-row-tile arrival counter

// ---------------- PTX helpers (plain sm_103-safe) ----------
__device__ __forceinline__ uint32_t smem_u32(const void* p) {
    uint32_t a;
    asm("{ .reg .u64 t; cvta.to.shared.u64 t, %1; cvt.u32.u64 %0, t; }" : "=r"(a) : "l"(p));
    return a;
}
#define CP_ASYNC16(dst, src) \
    asm volatile("cp.async.cg.shared.global [%0], [%1], 16;" :: "r"(dst), "l"(src))
#define CP_COMMIT() asm volatile("cp.async.commit_group;" ::: "memory")
#define CP_WAIT(n)  asm volatile("cp.async.wait_group %0;" :: "n"(n) : "memory")

#define LDMATRIX_X4(r0, r1, r2, r3, addr) \
    asm volatile("ldmatrix.sync.aligned.m8n8.x4.shared.b16 {%0,%1,%2,%3}, [%4];" \
                 : "=r"(r0), "=r"(r1), "=r"(r2), "=r"(r3) : "r"(addr))
#define LDMATRIX_X4_T(r0, r1, r2, r3, addr) \
    asm volatile("ldmatrix.sync.aligned.m8n8.x4.trans.shared.b16 {%0,%1,%2,%3}, [%4];" \
                 : "=r"(r0), "=r"(r1), "=r"(r2), "=r"(r3) : "r"(addr))

#define MMA_BF16(c, a, b0, b1) \
    asm volatile("mma.sync.aligned.m16n8k16.row.col.f32.bf16.bf16.f32 " \
                 "{%0,%1,%2,%3}, {%4,%5,%6,%7}, {%8,%9}, {%0,%1,%2,%3};" \
                 : "+f"((c)[0]), "+f"((c)[1]), "+f"((c)[2]), "+f"((c)[3]) \
                 : "r"((a)[0]), "r"((a)[1]), "r"((a)[2]), "r"((a)[3]), \
                   "r"(b0), "r"(b1))

__device__ __forceinline__ float gelu_tanh(float x) {
    float x3 = x * x * x;
    float t = tanhf(0.7978845608028654f * (x + 0.044715f * x3));
    return 0.5f * x * (1.0f + t);
}
__device__ __forceinline__ uint32_t packbf(float x, float y) {
    __nv_bfloat162 t = __float22bfloat162_rn(make_float2(x, y));
    return *(uint32_t*)&t;
}

// ---------- merged prep: ln1 (blocks 0..16383) + weight prep + cnt reset ---
__global__ void prep_kernel(const float* __restrict__ x, const float* __restrict__ g,
                            const float* __restrict__ b, bf16* __restrict__ y,
                            const float* __restrict__ wqkv, const float* __restrict__ wproj,
                            const float* __restrict__ w1, const float* __restrict__ w2,
                            bf16* __restrict__ o_qkv, bf16* __restrict__ o_proj,
                            bf16* __restrict__ o_w1, bf16* __restrict__ o_w2) {
    if (blockIdx.x < 16384) {
        int row = blockIdx.x * 8 + (threadIdx.x >> 5);
        int lane = threadIdx.x & 31;
        const float4* xr = (const float4*)(x + (size_t)row * C_DIM);
        float4 v0 = xr[lane * 2];
        float4 v1 = xr[lane * 2 + 1];
        float s = v0.x + v0.y + v0.z + v0.w + v1.x + v1.y + v1.z + v1.w;
        float ss = v0.x*v0.x + v0.y*v0.y + v0.z*v0.z + v0.w*v0.w
                 + v1.x*v1.x + v1.y*v1.y + v1.z*v1.z + v1.w*v1.w;
        #pragma unroll
        for (int o = 16; o > 0; o >>= 1) {
            s  += __shfl_xor_sync(0xffffffffu, s,  o);
            ss += __shfl_xor_sync(0xffffffffu, ss, o);
        }
        float mu = s * (1.0f / C_DIM);
        float var = ss * (1.0f / C_DIM) - mu * mu;
        float rstd = rsqrtf(var + 1e-5f);
        const float4* g4 = (const float4*)g;
        const float4* b4 = (const float4*)b;
        float4 ga = g4[lane * 2], gb = g4[lane * 2 + 1];
        float4 ba = b4[lane * 2], bb = b4[lane * 2 + 1];
        float o[8];
        o[0] = (v0.x - mu) * rstd * ga.x + ba.x;
        o[1] = (v0.y - mu) * rstd * ga.y + ba.y;
        o[2] = (v0.z - mu) * rstd * ga.z + ba.z;
        o[3] = (v0.w - mu) * rstd * ga.w + ba.w;
        o[4] = (v1.x - mu) * rstd * gb.x + bb.x;
        o[5] = (v1.y - mu) * rstd * gb.y + bb.y;
        o[6] = (v1.z - mu) * rstd * gb.z + bb.z;
        o[7] = (v1.w - mu) * rstd * gb.w + bb.w;
        uint32_t pk[4];
        #pragma unroll
        for (int i = 0; i < 4; i++) pk[i] = packbf(o[2*i], o[2*i+1]);
        *(uint4*)(y + (size_t)row * C_DIM + lane * 8) = make_uint4(pk[0], pk[1], pk[2], pk[3]);
    } else {
        if (blockIdx.x == 16384) {        // reset row-tile counters each launch
            for (int i = threadIdx.x; i < N_TOK / 128; i += 256) g_cnt[i] = 0;
        }
        int idx = (blockIdx.x - 16384) * 256 + threadIdx.x;
        if (idx < 196608) {
            int n = idx / 256, k = idx % 256;
            o_qkv[idx] = __float2bfloat16(wqkv[k * 768 + n]);
        } else if (idx < 262144) {
            int i = idx - 196608;
            int n = i / 256, k = i % 256;
            o_proj[i] = __float2bfloat16(wproj[k * 256 + n]);
        } else if (idx < 524288) {
            int i = idx - 262144;
            int n = i / 256, k = i % 256;
            o_w1[i] = __float2bfloat16(w1[k * 1024 + n]);
        } else {
            int i = idx - 524288;
            int n = i / 1024, k = i % 1024;
            o_w2[i] = __float2bfloat16(w2[k * 256 + n]);
        }
    }
}

// ---------------- HMMA GEMM (champion): BK=64, 3-stage, runtime K ----------
// EPI: 1 = bias+gelu (bf16 out), 2 = bias+residual (f32 out),
//      3 = bias+residual (f32 out) + fused LayerNorm -> out2 (bf16)
#define G_LDS 72
#define G_STAGE (2 * 128 * G_LDS)
#define G_SMEM (3 * G_STAGE * 2)

template <int EPI, bool OF32>
__global__ void __launch_bounds__(256, 2)
gemm_mma(const bf16* __restrict__ A, const bf16* __restrict__ BT,
         const float* __restrict__ bias, const float* __restrict__ res,
         void* __restrict__ Cout, int M, int Nn, int Kk,
         const float* __restrict__ lng, const float* __restrict__ lnb,
         bf16* __restrict__ out2) {
    constexpr int BK = 64;
    extern __shared__ bf16 smbuf[];
    __shared__ int s_last;

    const int tid = threadIdx.x;
    const int wid = tid >> 5, lane = tid & 31;
    const int wm = wid & 1, wn = wid >> 1;
    const int row0 = blockIdx.y * 128;
    const int col0 = blockIdx.x * 128;

    float acc[4][4][4];
    #pragma unroll
    for (int mi = 0; mi < 4; mi++)
        #pragma unroll
        for (int ni = 0; ni < 4; ni++)
            #pragma unroll
            for (int e = 0; e < 4; e++) acc[mi][ni][e] = 0.0f;

    auto load_stage = [&](int s, int k0) {
        bf16* As = smbuf + s * G_STAGE;
        bf16* Bs = As + 128 * G_LDS;
        #pragma unroll
        for (int i = 0; i < 4; i++) {
            int idx = tid + i * 256;
            int r = idx >> 3, c = (idx & 7) * 8;
            CP_ASYNC16(smem_u32(As + r * G_LDS + c), A + (size_t)(row0 + r) * Kk + k0 + c);
        }
        #pragma unroll
        for (int i = 0; i < 4; i++) {
            int idx = tid + i * 256;
            int r = idx >> 3, c = (idx & 7) * 8;
            CP_ASYNC16(smem_u32(Bs + r * G_LDS + c), BT + (size_t)(col0 + r) * Kk + k0 + c);
        }
    };

    const int nk = Kk / BK;
    load_stage(0, 0); CP_COMMIT();
    load_stage(1, BK); CP_COMMIT();

    for (int kt = 0; kt < nk; kt++) {
        int s = kt % 3;
        if (kt < nk - 1) CP_WAIT(1); else CP_WAIT(0);
        __syncthreads();
        if (kt + 2 < nk) { load_stage((kt + 2) % 3, (kt + 2) * BK); CP_COMMIT(); }

        bf16* As = smbuf + s * G_STAGE;
        bf16* Bs = As + 128 * G_LDS;
        #pragma unroll
        for (int ks = 0; ks < 4; ks++) {
            const int k0 = ks * 16;
            uint32_t a[4][4];
            #pragma unroll
            for (int mi = 0; mi < 4; mi++) {
                int r = wm * 64 + mi * 16 + (lane & 15);
                int c = k0 + ((lane >> 4) << 3);
                LDMATRIX_X4(a[mi][0], a[mi][1], a[mi][2], a[mi][3],
                            smem_u32(As + r * G_LDS + c));
            }
            uint32_t b[4][2];
            #pragma unroll
            for (int bi = 0; bi < 2; bi++) {
                int r = wn * 32 + bi * 16 + (lane & 15);
                int c = k0 + ((lane >> 4) << 3);
                uint32_t r0, r1, r2, r3;
                LDMATRIX_X4(r0, r1, r2, r3, smem_u32(Bs + r * G_LDS + c));
                b[2*bi][0] = r0; b[2*bi][1] = r2;
                b[2*bi+1][0] = r1; b[2*bi+1][1] = r3;
            }
            #pragma unroll
            for (int mi = 0; mi < 4; mi++)
                #pragma unroll
                for (int ni = 0; ni < 4; ni++)
                    MMA_BF16(acc[mi][ni], a[mi], b[ni][0], b[ni][1]);
        }
    }

    if (EPI != 3) {
        #pragma unroll
        for (int mi = 0; mi < 4; mi++) {
            #pragma unroll
            for (int ni = 0; ni < 4; ni++) {
                int r0 = row0 + wm * 64 + mi * 16 + (lane >> 2);
                int cc = col0 + wn * 32 + ni * 8 + (lane & 3) * 2;
                float2 bv = *(const float2*)(bias + cc);
                #pragma unroll
                for (int half = 0; half < 2; half++) {
                    int r = r0 + half * 8;
                    float vx = acc[mi][ni][2*half]   + bv.x;
                    float vy = acc[mi][ni][2*half+1] + bv.y;
                    if (EPI == 1) { vx = gelu_tanh(vx); vy = gelu_tanh(vy); }
                    if (EPI == 2) {
                        float2 rv = *(const float2*)(res + (size_t)r * Nn + cc);
                        vx += rv.x; vy += rv.y;
                    }
                    if (OF32) {
                        *(float2*)((float*)Cout + (size_t)r * Nn + cc) = make_float2(vx, vy);
                    } else {
                        *(uint32_t*)((bf16*)Cout + (size_t)r * Nn + cc) = packbf(vx, vy);
                    }
                }
            }
        }
    } else {
        // EPI 3: x = acc + bias + res (f32 out), per-row partial sums -> slots
        #pragma unroll
        for (int mi = 0; mi < 4; mi++) {
            #pragma unroll
            for (int half = 0; half < 2; half++) {
                int r = row0 + wm * 64 + mi * 16 + half * 8 + (lane >> 2);
                float s = 0.0f, q = 0.0f;
                #pragma unroll
                for (int ni = 0; ni < 4; ni++) {
                    int cc = col0 + wn * 32 + ni * 8 + (lane & 3) * 2;
                    float2 bv = *(const float2*)(bias + cc);
                    float2 rv = *(const float2*)(res + (size_t)r * Nn + cc);
                    float vx = acc[mi][ni][2*half]   + bv.x + rv.x;
                    float vy = acc[mi][ni][2*half+1] + bv.y + rv.y;
                    *(float2*)((float*)Cout + (size_t)r * Nn + cc) = make_float2(vx, vy);
                    s += vx + vy;
                    q += vx * vx + vy * vy;
                }
                s += __shfl_xor_sync(0xffffffffu, s, 1);
                q += __shfl_xor_sync(0xffffffffu, q, 1);
                s += __shfl_xor_sync(0xffffffffu, s, 2);
                q += __shfl_xor_sync(0xffffffffu, q, 2);
                if ((lane & 3) == 0)
                    g_rowpart[(size_t)r * 8 + blockIdx.x * 4 + wn] = make_float2(s, q);
            }
        }
        __threadfence();
        __syncthreads();
        if (tid == 0) {
            int old = atomicAdd(&g_cnt[blockIdx.y], 1);
            s_last = (old == 1);
        }
        __syncthreads();
        if (s_last) {
            // last CTA of this row-tile: LN over all 256 cols (x hot in L2)
            const float* xs = (const float*)Cout;
            for (int it = 0; it < 16; it++) {
                int r = row0 + wid + it * 8;
                float S = 0.0f, Q = 0.0f;
                #pragma unroll
                for (int sl = 0; sl < 8; sl++) {
                    float2 pp = g_rowpart[(size_t)r * 8 + sl];
                    S += pp.x; Q += pp.y;
                }
                float mu = S * (1.0f / 256.0f);
                float var = Q * (1.0f / 256.0f) - mu * mu;
                float rstd = rsqrtf(var + 1e-5f);
                const float4* xr = (const float4*)(xs + (size_t)r * 256);
                float4 v0 = xr[lane * 2];
                float4 v1 = xr[lane * 2 + 1];
                const float4* g4 = (const float4*)lng;
                const float4* b4 = (const float4*)lnb;
                float4 ga = g4[lane * 2], gb = g4[lane * 2 + 1];
                float4 ba = b4[lane * 2], bb = b4[lane * 2 + 1];
                float o[8];
                o[0] = (v0.x - mu) * rstd * ga.x + ba.x;
                o[1] = (v0.y - mu) * rstd * ga.y + ba.y;
                o[2] = (v0.z - mu) * rstd * ga.z + ba.z;
                o[3] = (v0.w - mu) * rstd * ga.w + ba.w;
                o[4] = (v1.x - mu) * rstd * gb.x + bb.x;
                o[5] = (v1.y - mu) * rstd * gb.y + bb.y;
                o[6] = (v1.z - mu) * rstd * gb.z + bb.z;
                o[7] = (v1.w - mu) * rstd * gb.w + bb.w;
                uint32_t pk[4];
                #pragma unroll
                for (int i = 0; i < 4; i++) pk[i] = packbf(o[2*i], o[2*i+1]);
                *(uint4*)(out2 + (size_t)r * 256 + lane * 8) =
                    make_uint4(pk[0], pk[1], pk[2], pk[3]);
            }
        }
    }
}

// ---------------- fused qkv-GEMM + attention (round-7 champion) ------------
#define FA_SMEM 200192

__global__ void __launch_bounds__(256)
fused_qkv_attn(const bf16* __restrict__ lnin, const bf16* __restrict__ wqkvT,
               const float* __restrict__ bqkv, const int* __restrict__ order,
               bf16* __restrict__ out) {
    extern __shared__ char sm[];
    bf16* pA = (bf16*)(sm);
    bf16* pW = (bf16*)(sm + 67584);
    bf16* pQ = (bf16*)(sm + 168960);
    bf16* pK = (bf16*)(sm + 179200);
    bf16* pV = (bf16*)(sm + 189440);
    int*  ptok = (int*)(sm + 199680);

    const int p = blockIdx.x;
    const int tid = threadIdx.x, wid = tid >> 5, lane = tid & 31;
    const int m0 = wid * 16;

    if (tid < 128) ptok[tid] = order[p * K_WIN + tid];

    #pragma unroll
    for (int i = 0; i < 16; i++) {
        int ch = tid + i * 256;
        int r = ch >> 5, c = (ch & 31) * 8;
        int token = order[p * K_WIN + r];
        CP_ASYNC16(smem_u32(pA + r * 264 + c), lnin + (size_t)token * C_DIM + c);
    }
    auto load_w = [&](int s, int h) {
        bf16* dst = pW + s * 25344;
        #pragma unroll
        for (int i = 0; i < 12; i++) {
            int ch = tid + i * 256;
            int r = ch >> 5, c = (ch & 31) * 8;
            int row_g = (r >> 5) * 256 + h * 32 + (r & 31);
            CP_ASYNC16(smem_u32(dst + r * 264 + c), wqkvT + (size_t)row_g * C_DIM + c);
        }
    };
    load_w(0, 0);
    CP_COMMIT();

    for (int h = 0; h < H_HEADS; h++) {
        if (h < H_HEADS - 1) { load_w((h + 1) & 1, h + 1); CP_COMMIT(); }
        if (h < H_HEADS - 1) CP_WAIT(1); else CP_WAIT(0);
        __syncthreads();

        float acc[12][4];
        #pragma unroll
        for (int j = 0; j < 12; j++)
            #pragma unroll
            for (int e = 0; e < 4; e++) acc[j][e] = 0.0f;
        const bf16* Wb = pW + (h & 1) * 25344;
        #pragma unroll
        for (int kk = 0; kk < 16; kk++) {
            const int k0 = kk * 16;
            uint32_t a[4];
            LDMATRIX_X4(a[0], a[1], a[2], a[3],
                        smem_u32(pA + (m0 + (lane & 15)) * 264 + k0 + ((lane >> 4) << 3)));
            #pragma unroll
            for (int nt = 0; nt < 6; nt++) {
                uint32_t r0, r1, r2, r3;
                LDMATRIX_X4(r0, r1, r2, r3,
                            smem_u32(Wb + (nt * 16 + (lane & 15)) * 264 + k0 + ((lane >> 4) << 3)));
                MMA_BF16(acc[2*nt],   a, r0, r2);
                MMA_BF16(acc[2*nt+1], a, r1, r3);
            }
        }
        {
            int rr = m0 + (lane >> 2);
            #pragma unroll
            for (int j = 0; j < 12; j++) {
                int n = j * 8 + (lane & 3) * 2;
                int sel = n >> 5, d = n & 31;
                float2 bv = *(const float2*)(bqkv + sel * 256 + h * 32 + d);
                bf16* dst = (sel == 0) ? pQ : (sel == 1) ? pK : pV;
                *(uint32_t*)(dst + rr * 40 + d)       = packbf(acc[j][0] + bv.x, acc[j][1] + bv.y);
                *(uint32_t*)(dst + (rr + 8) * 40 + d) = packbf(acc[j][2] + bv.x, acc[j][3] + bv.y);
            }
        }
        __syncthreads();

        float sacc[16][4];
        #pragma unroll
        for (int nt = 0; nt < 16; nt++)
            #pragma unroll
            for (int e = 0; e < 4; e++) sacc[nt][e] = 0.0f;
        #pragma unroll
        for (int ksx = 0; ksx < 2; ksx++) {
            const int k0 = ksx * 16;
            uint32_t a[4];
            LDMATRIX_X4(a[0], a[1], a[2], a[3],
                        smem_u32(pQ + (m0 + (lane & 15)) * 40 + k0 + ((lane >> 4) << 3)));
            #pragma unroll
            for (int t = 0; t < 8; t++) {
                uint32_t r0, r1, r2, r3;
                LDMATRIX_X4(r0, r1, r2, r3,
                            smem_u32(pK + (t * 16 + (lane & 15)) * 40 + k0 + ((lane >> 4) << 3)));
                MMA_BF16(sacc[2*t],   a, r0, r2);
                MMA_BF16(sacc[2*t+1], a, r1, r3);
            }
        }

        float m_lo = -INFINITY, m_hi = -INFINITY;
        #pragma unroll
        for (int nt = 0; nt < 16; nt++) {
            #pragma unroll
            for (int e = 0; e < 4; e++) sacc[nt][e] *= SCALE_ATTN;
            m_lo = fmaxf(m_lo, fmaxf(sacc[nt][0], sacc[nt][1]));
            m_hi = fmaxf(m_hi, fmaxf(sacc[nt][2], sacc[nt][3]));
        }
        m_lo = fmaxf(m_lo, __shfl_xor_sync(0xffffffffu, m_lo, 1));
        m_lo = fmaxf(m_lo, __shfl_xor_sync(0xffffffffu, m_lo, 2));
        m_hi = fmaxf(m_hi, __shfl_xor_sync(0xffffffffu, m_hi, 1));
        m_hi = fmaxf(m_hi, __shfl_xor_sync(0xffffffffu, m_hi, 2));

        float l_lo = 0.0f, l_hi = 0.0f;
        uint32_t pf[16][2];
        #pragma unroll
        for (int nt = 0; nt < 16; nt++) {
            float e0 = __expf(sacc[nt][0] - m_lo);
            float e1 = __expf(sacc[nt][1] - m_lo);
            float e2 = __expf(sacc[nt][2] - m_hi);
            float e3 = __expf(sacc[nt][3] - m_hi);
            l_lo += e0 + e1;
            l_hi += e2 + e3;
            pf[nt][0] = packbf(e0, e1);
            pf[nt][1] = packbf(e2, e3);
        }
        l_lo += __shfl_xor_sync(0xffffffffu, l_lo, 1);
        l_lo += __shfl_xor_sync(0xffffffffu, l_lo, 2);
        l_hi += __shfl_xor_sync(0xffffffffu, l_hi, 1);
        l_hi += __shfl_xor_sync(0xffffffffu, l_hi, 2);

        float acco[4][4];
        #pragma unroll
        for (int nt = 0; nt < 4; nt++)
            #pragma unroll
            for (int e = 0; e < 4; e++) acco[nt][e] = 0.0f;
        #pragma unroll
        for (int kk = 0; kk < 8; kk++) {
            uint32_t a[4] = {pf[2*kk][0], pf[2*kk][1], pf[2*kk+1][0], pf[2*kk+1][1]};
            uint32_t r0, r1, r2, r3;
            LDMATRIX_X4_T(r0, r1, r2, r3,
                          smem_u32(pV + (kk * 16 + (lane & 15)) * 40 + ((lane >> 4) << 3)));
            MMA_BF16(acco[0], a, r0, r1);
            MMA_BF16(acco[1], a, r2, r3);
            uint32_t s0, s1, s2, s3;
            LDMATRIX_X4_T(s0, s1, s2, s3,
                          smem_u32(pV + (kk * 16 + (lane & 15)) * 40 + 16 + ((lane >> 4) << 3)));
            MMA_BF16(acco[2], a, s0, s1);
            MMA_BF16(acco[3], a, s2, s3);
        }

        float inv_lo = 1.0f / l_lo, inv_hi = 1.0f / l_hi;
        int r_lo = m0 + (lane >> 2);
        int tok_lo = ptok[r_lo], tok_hi = ptok[r_lo + 8];
        bf16* o_lo = out + (size_t)tok_lo * C_DIM + h * D_HEAD + (lane & 3) * 2;
        bf16* o_hi = out + (size_t)tok_hi * C_DIM + h * D_HEAD + (lane & 3) * 2;
        #pragma unroll
        for (int nt = 0; nt < 4; nt++) {
            *(uint32_t*)(o_lo + nt * 8) = packbf(acco[nt][0] * inv_lo, acco[nt][1] * inv_lo);
            *(uint32_t*)(o_hi + nt * 8) = packbf(acco[nt][2] * inv_hi, acco[nt][3] * inv_hi);
        }
    }
}

// ---------------------------- launch ---------------------------------------
extern "C" void kernel_launch(void* const* d_in, const int* in_sizes, int n_in,
                              void* d_out, int out_size) {
    const float* feat   = (const float*)d_in[0];
    const float* ln1_g  = (const float*)d_in[1];
    const float* ln1_b  = (const float*)d_in[2];
    const float* w_qkv  = (const float*)d_in[3];
    const float* b_qkv  = (const float*)d_in[4];
    const float* w_proj = (const float*)d_in[5];
    const float* b_proj = (const float*)d_in[6];
    const float* ln2_g  = (const float*)d_in[7];
    const float* ln2_b  = (const float*)d_in[8];
    const float* w1     = (const float*)d_in[9];
    const float* b1     = (const float*)d_in[10];
    const float* w2     = (const float*)d_in[11];
    const float* b2     = (const float*)d_in[12];
    const int*   order  = (const int*)d_in[13];

    bf16 *p_ln, *p_attn, *p_mid, *p_wqkvT, *p_wprojT, *p_w1T, *p_w2T;
    float* p_x;
    cudaGetSymbolAddress((void**)&p_ln,     g_ln);
    cudaGetSymbolAddress((void**)&p_attn,   g_attn);
    cudaGetSymbolAddress((void**)&p_x,      g_x);
    cudaGetSymbolAddress((void**)&p_mid,    g_mid);
    cudaGetSymbolAddress((void**)&p_wqkvT,  g_wqkvT);
    cudaGetSymbolAddress((void**)&p_wprojT, g_wprojT);
    cudaGetSymbolAddress((void**)&p_w1T,    g_w1T);
    cudaGetSymbolAddress((void**)&p_w2T,    g_w2T);

    cudaFuncSetAttribute(fused_qkv_attn, cudaFuncAttributeMaxDynamicSharedMemorySize, FA_SMEM);
    cudaFuncSetAttribute(gemm_mma<3, true>,  cudaFuncAttributeMaxDynamicSharedMemorySize, G_SMEM);
    cudaFuncSetAttribute(gemm_mma<1, false>, cudaFuncAttributeMaxDynamicSharedMemorySize, G_SMEM);
    cudaFuncSetAttribute(gemm_mma<2, true>,  cudaFuncAttributeMaxDynamicSharedMemorySize, G_SMEM);

    // 1. merged ln1 + weight prep + counter reset (one launch)
    prep_kernel<<<16384 + 3072, 256>>>(feat, ln1_g, ln1_b, p_ln,
                                       w_qkv, w_proj, w1, w2,
                                       p_wqkvT, p_wprojT, p_w1T, p_w2T);
    // 2. fused qkv + attention -> g_attn (bf16, original order)
    fused_qkv_attn<<<P_TILES, 256, FA_SMEM>>>(p_ln, p_wqkvT, b_qkv, order, p_attn);
    // 3. proj + residual + fused LN2: x (f32) and ln2-out (bf16) in one kernel
    gemm_mma<3, true><<<dim3(2, N_TOK / 128), 256, G_SMEM>>>(
        p_attn, p_wprojT, b_proj, feat, p_x, N_TOK, C_DIM, C_DIM,
        ln2_g, ln2_b, p_ln);
    // 4. mid = gelu(ln2 @ w1 + b1)
    gemm_mma<1, false><<<dim3(8, N_TOK / 128), 256, G_SMEM>>>(
        p_ln, p_w1T, b1, nullptr, p_mid, N_TOK, HID_DIM, C_DIM,
        nullptr, nullptr, nullptr);
    // 5. out = x + mid @ w2 + b2  (f32)
    gemm_mma<2, true><<<dim3(2, N_TOK / 128), 256, G_SMEM>>>(
        p_mid, p_w2T, b2, p_x, (float*)d_out, N_TOK, C_DIM, HID_DIM,
        nullptr, nullptr, nullptr);
}

// round 17
// speedup vs baseline: 1.1705x; 1.0566x over previous
#include <cuda_runtime.h>
#include <cuda_bf16.h>
#include <math.h>
#include <stdint.h>

#define N_TOK 131072
#define C_DIM 256
#define HID_DIM 1024
#define H_HEADS 8
#define D_HEAD 32
#define K_WIN 128
#define P_TILES (N_TOK / K_WIN)
#define SCALE_ATTN 0.17677669529663687f

typedef __nv_bfloat16 bf16;

// ---------------- scratch (device globals) ----------------
__device__ bf16  g_ln[N_TOK * C_DIM];
__device__ bf16  g_attn[N_TOK * C_DIM];
__device__ float g_x[N_TOK * C_DIM];
__device__ bf16  g_mid[N_TOK * HID_DIM];
__device__ bf16  g_wqkvT[3 * C_DIM * C_DIM];
__device__ bf16  g_wprojT[C_DIM * C_DIM];
__device__ bf16  g_w1T[HID_DIM * C_DIM];
__device__ bf16  g_w2T[C_DIM * HID_DIM];
__device__ float2 g_rowpart[N_TOK * 8];      // 8 deterministic slots per row
__device__ int    g_cnt[N_TOK / 128];        // per-row-tile arrival counter

// ---------------- PTX helpers (plain sm_103-safe) ----------
__device__ __forceinline__ uint32_t smem_u32(const void* p) {
    uint32_t a;
    asm("{ .reg .u64 t; cvta.to.shared.u64 t, %1; cvt.u32.u64 %0, t; }" : "=r"(a) : "l"(p));
    return a;
}
#define CP_ASYNC16(dst, src) \
    asm volatile("cp.async.cg.shared.global [%0], [%1], 16;" :: "r"(dst), "l"(src))
#define CP_COMMIT() asm volatile("cp.async.commit_group;" ::: "memory")
#define CP_WAIT(n)  asm volatile("cp.async.wait_group %0;" :: "n"(n) : "memory")

#define LDMATRIX_X4(r0, r1, r2, r3, addr) \
    asm volatile("ldmatrix.sync.aligned.m8n8.x4.shared.b16 {%0,%1,%2,%3}, [%4];" \
                 : "=r"(r0), "=r"(r1), "=r"(r2), "=r"(r3) : "r"(addr))
#define LDMATRIX_X4_T(r0, r1, r2, r3, addr) \
    asm volatile("ldmatrix.sync.aligned.m8n8.x4.trans.shared.b16 {%0,%1,%2,%3}, [%4];" \
                 : "=r"(r0), "=r"(r1), "=r"(r2), "=r"(r3) : "r"(addr))

#define MMA_BF16(c, a, b0, b1) \
    asm volatile("mma.sync.aligned.m16n8k16.row.col.f32.bf16.bf16.f32 " \
                 "{%0,%1,%2,%3}, {%4,%5,%6,%7}, {%8,%9}, {%0,%1,%2,%3};" \
                 : "+f"((c)[0]), "+f"((c)[1]), "+f"((c)[2]), "+f"((c)[3]) \
                 : "r"((a)[0]), "r"((a)[1]), "r"((a)[2]), "r"((a)[3]), \
                   "r"(b0), "r"(b1))

// HW tanh (sm_75+): 1 MUFU instruction, rel err ~2^-11 — negligible vs the
// bf16 rounding (~4e-3) applied to the gelu output when storing g_mid.
__device__ __forceinline__ float gelu_tanh(float x) {
    float x3 = x * x * x;
    float u = 0.7978845608028654f * (x + 0.044715f * x3);
    float t;
    asm("tanh.approx.f32 %0, %1;" : "=f"(t) : "f"(u));
    return 0.5f * x * (1.0f + t);
}
__device__ __forceinline__ uint32_t packbf(float x, float y) {
    __nv_bfloat162 t = __float22bfloat162_rn(make_float2(x, y));
    return *(uint32_t*)&t;
}

// ---------- merged prep: ln1 (blocks 0..16383) + weight prep + cnt reset ---
__global__ void prep_kernel(const float* __restrict__ x, const float* __restrict__ g,
                            const float* __restrict__ b, bf16* __restrict__ y,
                            const float* __restrict__ wqkv, const float* __restrict__ wproj,
                            const float* __restrict__ w1, const float* __restrict__ w2,
                            bf16* __restrict__ o_qkv, bf16* __restrict__ o_proj,
                            bf16* __restrict__ o_w1, bf16* __restrict__ o_w2) {
    if (blockIdx.x < 16384) {
        int row = blockIdx.x * 8 + (threadIdx.x >> 5);
        int lane = threadIdx.x & 31;
        const float4* xr = (const float4*)(x + (size_t)row * C_DIM);
        float4 v0 = xr[lane * 2];
        float4 v1 = xr[lane * 2 + 1];
        float s = v0.x + v0.y + v0.z + v0.w + v1.x + v1.y + v1.z + v1.w;
        float ss = v0.x*v0.x + v0.y*v0.y + v0.z*v0.z + v0.w*v0.w
                 + v1.x*v1.x + v1.y*v1.y + v1.z*v1.z + v1.w*v1.w;
        #pragma unroll
        for (int o = 16; o > 0; o >>= 1) {
            s  += __shfl_xor_sync(0xffffffffu, s,  o);
            ss += __shfl_xor_sync(0xffffffffu, ss, o);
        }
        float mu = s * (1.0f / C_DIM);
        float var = ss * (1.0f / C_DIM) - mu * mu;
        float rstd = rsqrtf(var + 1e-5f);
        const float4* g4 = (const float4*)g;
        const float4* b4 = (const float4*)b;
        float4 ga = g4[lane * 2], gb = g4[lane * 2 + 1];
        float4 ba = b4[lane * 2], bb = b4[lane * 2 + 1];
        float o[8];
        o[0] = (v0.x - mu) * rstd * ga.x + ba.x;
        o[1] = (v0.y - mu) * rstd * ga.y + ba.y;
        o[2] = (v0.z - mu) * rstd * ga.z + ba.z;
        o[3] = (v0.w - mu) * rstd * ga.w + ba.w;
        o[4] = (v1.x - mu) * rstd * gb.x + bb.x;
        o[5] = (v1.y - mu) * rstd * gb.y + bb.y;
        o[6] = (v1.z - mu) * rstd * gb.z + bb.z;
        o[7] = (v1.w - mu) * rstd * gb.w + bb.w;
        uint32_t pk[4];
        #pragma unroll
        for (int i = 0; i < 4; i++) pk[i] = packbf(o[2*i], o[2*i+1]);
        *(uint4*)(y + (size_t)row * C_DIM + lane * 8) = make_uint4(pk[0], pk[1], pk[2], pk[3]);
    } else {
        if (blockIdx.x == 16384) {        // reset row-tile counters each launch
            for (int i = threadIdx.x; i < N_TOK / 128; i += 256) g_cnt[i] = 0;
        }
        int idx = (blockIdx.x - 16384) * 256 + threadIdx.x;
        if (idx < 196608) {
            int n = idx / 256, k = idx % 256;
            o_qkv[idx] = __float2bfloat16(wqkv[k * 768 + n]);
        } else if (idx < 262144) {
            int i = idx - 196608;
            int n = i / 256, k = i % 256;
            o_proj[i] = __float2bfloat16(wproj[k * 256 + n]);
        } else if (idx < 524288) {
            int i = idx - 262144;
            int n = i / 256, k = i % 256;
            o_w1[i] = __float2bfloat16(w1[k * 1024 + n]);
        } else {
            int i = idx - 524288;
            int n = i / 1024, k = i % 1024;
            o_w2[i] = __float2bfloat16(w2[k * 256 + n]);
        }
    }
}

// ---------------- HMMA GEMM (champion): BK=64, 3-stage, runtime K ----------
// EPI: 1 = bias+gelu (bf16 out), 2 = bias+residual (f32 out),
//      3 = bias+residual (f32 out) + fused LayerNorm -> out2 (bf16)
#define G_LDS 72
#define G_STAGE (2 * 128 * G_LDS)
#define G_SMEM (3 * G_STAGE * 2)

template <int EPI, bool OF32>
__global__ void __launch_bounds__(256, 2)
gemm_mma(const bf16* __restrict__ A, const bf16* __restrict__ BT,
         const float* __restrict__ bias, const float* __restrict__ res,
         void* __restrict__ Cout, int M, int Nn, int Kk,
         const float* __restrict__ lng, const float* __restrict__ lnb,
         bf16* __restrict__ out2) {
    constexpr int BK = 64;
    extern __shared__ bf16 smbuf[];
    __shared__ int s_last;

    const int tid = threadIdx.x;
    const int wid = tid >> 5, lane = tid & 31;
    const int wm = wid & 1, wn = wid >> 1;
    const int row0 = blockIdx.y * 128;
    const int col0 = blockIdx.x * 128;

    float acc[4][4][4];
    #pragma unroll
    for (int mi = 0; mi < 4; mi++)
        #pragma unroll
        for (int ni = 0; ni < 4; ni++)
            #pragma unroll
            for (int e = 0; e < 4; e++) acc[mi][ni][e] = 0.0f;

    auto load_stage = [&](int s, int k0) {
        bf16* As = smbuf + s * G_STAGE;
        bf16* Bs = As + 128 * G_LDS;
        #pragma unroll
        for (int i = 0; i < 4; i++) {
            int idx = tid + i * 256;
            int r = idx >> 3, c = (idx & 7) * 8;
            CP_ASYNC16(smem_u32(As + r * G_LDS + c), A + (size_t)(row0 + r) * Kk + k0 + c);
        }
        #pragma unroll
        for (int i = 0; i < 4; i++) {
            int idx = tid + i * 256;
            int r = idx >> 3, c = (idx & 7) * 8;
            CP_ASYNC16(smem_u32(Bs + r * G_LDS + c), BT + (size_t)(col0 + r) * Kk + k0 + c);
        }
    };

    const int nk = Kk / BK;
    load_stage(0, 0); CP_COMMIT();
    load_stage(1, BK); CP_COMMIT();

    for (int kt = 0; kt < nk; kt++) {
        int s = kt % 3;
        if (kt < nk - 1) CP_WAIT(1); else CP_WAIT(0);
        __syncthreads();
        if (kt + 2 < nk) { load_stage((kt + 2) % 3, (kt + 2) * BK); CP_COMMIT(); }

        bf16* As = smbuf + s * G_STAGE;
        bf16* Bs = As + 128 * G_LDS;
        #pragma unroll
        for (int ks = 0; ks < 4; ks++) {
            const int k0 = ks * 16;
            uint32_t a[4][4];
            #pragma unroll
            for (int mi = 0; mi < 4; mi++) {
                int r = wm * 64 + mi * 16 + (lane & 15);
                int c = k0 + ((lane >> 4) << 3);
                LDMATRIX_X4(a[mi][0], a[mi][1], a[mi][2], a[mi][3],
                            smem_u32(As + r * G_LDS + c));
            }
            uint32_t b[4][2];
            #pragma unroll
            for (int bi = 0; bi < 2; bi++) {
                int r = wn * 32 + bi * 16 + (lane & 15);
                int c = k0 + ((lane >> 4) << 3);
                uint32_t r0, r1, r2, r3;
                LDMATRIX_X4(r0, r1, r2, r3, smem_u32(Bs + r * G_LDS + c));
                b[2*bi][0] = r0; b[2*bi][1] = r2;
                b[2*bi+1][0] = r1; b[2*bi+1][1] = r3;
            }
            #pragma unroll
            for (int mi = 0; mi < 4; mi++)
                #pragma unroll
                for (int ni = 0; ni < 4; ni++)
                    MMA_BF16(acc[mi][ni], a[mi], b[ni][0], b[ni][1]);
        }
    }

    if (EPI != 3) {
        #pragma unroll
        for (int mi = 0; mi < 4; mi++) {
            #pragma unroll
            for (int ni = 0; ni < 4; ni++) {
                int r0 = row0 + wm * 64 + mi * 16 + (lane >> 2);
                int cc = col0 + wn * 32 + ni * 8 + (lane & 3) * 2;
                float2 bv = *(const float2*)(bias + cc);
                #pragma unroll
                for (int half = 0; half < 2; half++) {
                    int r = r0 + half * 8;
                    float vx = acc[mi][ni][2*half]   + bv.x;
                    float vy = acc[mi][ni][2*half+1] + bv.y;
                    if (EPI == 1) { vx = gelu_tanh(vx); vy = gelu_tanh(vy); }
                    if (EPI == 2) {
                        float2 rv = *(const float2*)(res + (size_t)r * Nn + cc);
                        vx += rv.x; vy += rv.y;
                    }
                    if (OF32) {
                        *(float2*)((float*)Cout + (size_t)r * Nn + cc) = make_float2(vx, vy);
                    } else {
                        *(uint32_t*)((bf16*)Cout + (size_t)r * Nn + cc) = packbf(vx, vy);
                    }
                }
            }
        }
    } else {
        // EPI 3: x = acc + bias + res (f32 out), per-row partial sums -> slots
        #pragma unroll
        for (int mi = 0; mi < 4; mi++) {
            #pragma unroll
            for (int half = 0; half < 2; half++) {
                int r = row0 + wm * 64 + mi * 16 + half * 8 + (lane >> 2);
                float s = 0.0f, q = 0.0f;
                #pragma unroll
                for (int ni = 0; ni < 4; ni++) {
                    int cc = col0 + wn * 32 + ni * 8 + (lane & 3) * 2;
                    float2 bv = *(const float2*)(bias + cc);
                    float2 rv = *(const float2*)(res + (size_t)r * Nn + cc);
                    float vx = acc[mi][ni][2*half]   + bv.x + rv.x;
                    float vy = acc[mi][ni][2*half+1] + bv.y + rv.y;
                    *(float2*)((float*)Cout + (size_t)r * Nn + cc) = make_float2(vx, vy);
                    s += vx + vy;
                    q += vx * vx + vy * vy;
                }
                s += __shfl_xor_sync(0xffffffffu, s, 1);
                q += __shfl_xor_sync(0xffffffffu, q, 1);
                s += __shfl_xor_sync(0xffffffffu, s, 2);
                q += __shfl_xor_sync(0xffffffffu, q, 2);
                if ((lane & 3) == 0)
                    g_rowpart[(size_t)r * 8 + blockIdx.x * 4 + wn] = make_float2(s, q);
            }
        }
        __threadfence();
        __syncthreads();
        if (tid == 0) {
            int old = atomicAdd(&g_cnt[blockIdx.y], 1);
            s_last = (old == 1);
        }
        __syncthreads();
        if (s_last) {
            // last CTA of this row-tile: LN over all 256 cols (x hot in L2)
            const float* xs = (const float*)Cout;
            for (int it = 0; it < 16; it++) {
                int r = row0 + wid + it * 8;
                float S = 0.0f, Q = 0.0f;
                #pragma unroll
                for (int sl = 0; sl < 8; sl++) {
                    float2 pp = g_rowpart[(size_t)r * 8 + sl];
                    S += pp.x; Q += pp.y;
                }
                float mu = S * (1.0f / 256.0f);
                float var = Q * (1.0f / 256.0f) - mu * mu;
                float rstd = rsqrtf(var + 1e-5f);
                const float4* xr = (const float4*)(xs + (size_t)r * 256);
                float4 v0 = xr[lane * 2];
                float4 v1 = xr[lane * 2 + 1];
                const float4* g4 = (const float4*)lng;
                const float4* b4 = (const float4*)lnb;
                float4 ga = g4[lane * 2], gb = g4[lane * 2 + 1];
                float4 ba = b4[lane * 2], bb = b4[lane * 2 + 1];
                float o[8];
                o[0] = (v0.x - mu) * rstd * ga.x + ba.x;
                o[1] = (v0.y - mu) * rstd * ga.y + ba.y;
                o[2] = (v0.z - mu) * rstd * ga.z + ba.z;
                o[3] = (v0.w - mu) * rstd * ga.w + ba.w;
                o[4] = (v1.x - mu) * rstd * gb.x + bb.x;
                o[5] = (v1.y - mu) * rstd * gb.y + bb.y;
                o[6] = (v1.z - mu) * rstd * gb.z + bb.z;
                o[7] = (v1.w - mu) * rstd * gb.w + bb.w;
                uint32_t pk[4];
                #pragma unroll
                for (int i = 0; i < 4; i++) pk[i] = packbf(o[2*i], o[2*i+1]);
                *(uint4*)(out2 + (size_t)r * 256 + lane * 8) =
                    make_uint4(pk[0], pk[1], pk[2], pk[3]);
            }
        }
    }
}

// ---------------- fused qkv-GEMM + attention (round-7 champion) ------------
#define FA_SMEM 200192

__global__ void __launch_bounds__(256)
fused_qkv_attn(const bf16* __restrict__ lnin, const bf16* __restrict__ wqkvT,
               const float* __restrict__ bqkv, const int* __restrict__ order,
               bf16* __restrict__ out) {
    extern __shared__ char sm[];
    bf16* pA = (bf16*)(sm);
    bf16* pW = (bf16*)(sm + 67584);
    bf16* pQ = (bf16*)(sm + 168960);
    bf16* pK = (bf16*)(sm + 179200);
    bf16* pV = (bf16*)(sm + 189440);
    int*  ptok = (int*)(sm + 199680);

    const int p = blockIdx.x;
    const int tid = threadIdx.x, wid = tid >> 5, lane = tid & 31;
    const int m0 = wid * 16;

    if (tid < 128) ptok[tid] = order[p * K_WIN + tid];

    #pragma unroll
    for (int i = 0; i < 16; i++) {
        int ch = tid + i * 256;
        int r = ch >> 5, c = (ch & 31) * 8;
        int token = order[p * K_WIN + r];
        CP_ASYNC16(smem_u32(pA + r * 264 + c), lnin + (size_t)token * C_DIM + c);
    }
    auto load_w = [&](int s, int h) {
        bf16* dst = pW + s * 25344;
        #pragma unroll
        for (int i = 0; i < 12; i++) {
            int ch = tid + i * 256;
            int r = ch >> 5, c = (ch & 31) * 8;
            int row_g = (r >> 5) * 256 + h * 32 + (r & 31);
            CP_ASYNC16(smem_u32(dst + r * 264 + c), wqkvT + (size_t)row_g * C_DIM + c);
        }
    };
    load_w(0, 0);
    CP_COMMIT();

    for (int h = 0; h < H_HEADS; h++) {
        if (h < H_HEADS - 1) { load_w((h + 1) & 1, h + 1); CP_COMMIT(); }
        if (h < H_HEADS - 1) CP_WAIT(1); else CP_WAIT(0);
        __syncthreads();

        float acc[12][4];
        #pragma unroll
        for (int j = 0; j < 12; j++)
            #pragma unroll
            for (int e = 0; e < 4; e++) acc[j][e] = 0.0f;
        const bf16* Wb = pW + (h & 1) * 25344;
        #pragma unroll
        for (int kk = 0; kk < 16; kk++) {
            const int k0 = kk * 16;
            uint32_t a[4];
            LDMATRIX_X4(a[0], a[1], a[2], a[3],
                        smem_u32(pA + (m0 + (lane & 15)) * 264 + k0 + ((lane >> 4) << 3)));
            #pragma unroll
            for (int nt = 0; nt < 6; nt++) {
                uint32_t r0, r1, r2, r3;
                LDMATRIX_X4(r0, r1, r2, r3,
                            smem_u32(Wb + (nt * 16 + (lane & 15)) * 264 + k0 + ((lane >> 4) << 3)));
                MMA_BF16(acc[2*nt],   a, r0, r2);
                MMA_BF16(acc[2*nt+1], a, r1, r3);
            }
        }
        {
            int rr = m0 + (lane >> 2);
            #pragma unroll
            for (int j = 0; j < 12; j++) {
                int n = j * 8 + (lane & 3) * 2;
                int sel = n >> 5, d = n & 31;
                float2 bv = *(const float2*)(bqkv + sel * 256 + h * 32 + d);
                bf16* dst = (sel == 0) ? pQ : (sel == 1) ? pK : pV;
                *(uint32_t*)(dst + rr * 40 + d)       = packbf(acc[j][0] + bv.x, acc[j][1] + bv.y);
                *(uint32_t*)(dst + (rr + 8) * 40 + d) = packbf(acc[j][2] + bv.x, acc[j][3] + bv.y);
            }
        }
        __syncthreads();

        float sacc[16][4];
        #pragma unroll
        for (int nt = 0; nt < 16; nt++)
            #pragma unroll
            for (int e = 0; e < 4; e++) sacc[nt][e] = 0.0f;
        #pragma unroll
        for (int ksx = 0; ksx < 2; ksx++) {
            const int k0 = ksx * 16;
            uint32_t a[4];
            LDMATRIX_X4(a[0], a[1], a[2], a[3],
                        smem_u32(pQ + (m0 + (lane & 15)) * 40 + k0 + ((lane >> 4) << 3)));
            #pragma unroll
            for (int t = 0; t < 8; t++) {
                uint32_t r0, r1, r2, r3;
                LDMATRIX_X4(r0, r1, r2, r3,
                            smem_u32(pK + (t * 16 + (lane & 15)) * 40 + k0 + ((lane >> 4) << 3)));
                MMA_BF16(sacc[2*t],   a, r0, r2);
                MMA_BF16(sacc[2*t+1], a, r1, r3);
            }
        }

        float m_lo = -INFINITY, m_hi = -INFINITY;
        #pragma unroll
        for (int nt = 0; nt < 16; nt++) {
            #pragma unroll
            for (int e = 0; e < 4; e++) sacc[nt][e] *= SCALE_ATTN;
            m_lo = fmaxf(m_lo, fmaxf(sacc[nt][0], sacc[nt][1]));
            m_hi = fmaxf(m_hi, fmaxf(sacc[nt][2], sacc[nt][3]));
        }
        m_lo = fmaxf(m_lo, __shfl_xor_sync(0xffffffffu, m_lo, 1));
        m_lo = fmaxf(m_lo, __shfl_xor_sync(0xffffffffu, m_lo, 2));
        m_hi = fmaxf(m_hi, __shfl_xor_sync(0xffffffffu, m_hi, 1));
        m_hi = fmaxf(m_hi, __shfl_xor_sync(0xffffffffu, m_hi, 2));

        float l_lo = 0.0f, l_hi = 0.0f;
        uint32_t pf[16][2];
        #pragma unroll
        for (int nt = 0; nt < 16; nt++) {
            float e0 = __expf(sacc[nt][0] - m_lo);
            float e1 = __expf(sacc[nt][1] - m_lo);
            float e2 = __expf(sacc[nt][2] - m_hi);
            float e3 = __expf(sacc[nt][3] - m_hi);
            l_lo += e0 + e1;
            l_hi += e2 + e3;
            pf[nt][0] = packbf(e0, e1);
            pf[nt][1] = packbf(e2, e3);
        }
        l_lo += __shfl_xor_sync(0xffffffffu, l_lo, 1);
        l_lo += __shfl_xor_sync(0xffffffffu, l_lo, 2);
        l_hi += __shfl_xor_sync(0xffffffffu, l_hi, 1);
        l_hi += __shfl_xor_sync(0xffffffffu, l_hi, 2);

        float acco[4][4];
        #pragma unroll
        for (int nt = 0; nt < 4; nt++)
            #pragma unroll
            for (int e = 0; e < 4; e++) acco[nt][e] = 0.0f;
        #pragma unroll
        for (int kk = 0; kk < 8; kk++) {
            uint32_t a[4] = {pf[2*kk][0], pf[2*kk][1], pf[2*kk+1][0], pf[2*kk+1][1]};
            uint32_t r0, r1, r2, r3;
            LDMATRIX_X4_T(r0, r1, r2, r3,
                          smem_u32(pV + (kk * 16 + (lane & 15)) * 40 + ((lane >> 4) << 3)));
            MMA_BF16(acco[0], a, r0, r1);
            MMA_BF16(acco[1], a, r2, r3);
            uint32_t s0, s1, s2, s3;
            LDMATRIX_X4_T(s0, s1, s2, s3,
                          smem_u32(pV + (kk * 16 + (lane & 15)) * 40 + 16 + ((lane >> 4) << 3)));
            MMA_BF16(acco[2], a, s0, s1);
            MMA_BF16(acco[3], a, s2, s3);
        }

        float inv_lo = 1.0f / l_lo, inv_hi = 1.0f / l_hi;
        int r_lo = m0 + (lane >> 2);
        int tok_lo = ptok[r_lo], tok_hi = ptok[r_lo + 8];
        bf16* o_lo = out + (size_t)tok_lo * C_DIM + h * D_HEAD + (lane & 3) * 2;
        bf16* o_hi = out + (size_t)tok_hi * C_DIM + h * D_HEAD + (lane & 3) * 2;
        #pragma unroll
        for (int nt = 0; nt < 4; nt++) {
            *(uint32_t*)(o_lo + nt * 8) = packbf(acco[nt][0] * inv_lo, acco[nt][1] * inv_lo);
            *(uint32_t*)(o_hi + nt * 8) = packbf(acco[nt][2] * inv_hi, acco[nt][3] * inv_hi);
        }
    }
}

// ---------------------------- launch ---------------------------------------
extern "C" void kernel_launch(void* const* d_in, const int* in_sizes, int n_in,
                              void* d_out, int out_size) {
    const float* feat   = (const float*)d_in[0];
    const float* ln1_g  = (const float*)d_in[1];
    const float* ln1_b  = (const float*)d_in[2];
    const float* w_qkv  = (const float*)d_in[3];
    const float* b_qkv  = (const float*)d_in[4];
    const float* w_proj = (const float*)d_in[5];
    const float* b_proj = (const float*)d_in[6];
    const float* ln2_g  = (const float*)d_in[7];
    const float* ln2_b  = (const float*)d_in[8];
    const float* w1     = (const float*)d_in[9];
    const float* b1     = (const float*)d_in[10];
    const float* w2     = (const float*)d_in[11];
    const float* b2     = (const float*)d_in[12];
    const int*   order  = (const int*)d_in[13];

    bf16 *p_ln, *p_attn, *p_mid, *p_wqkvT, *p_wprojT, *p_w1T, *p_w2T;
    float* p_x;
    cudaGetSymbolAddress((void**)&p_ln,     g_ln);
    cudaGetSymbolAddress((void**)&p_attn,   g_attn);
    cudaGetSymbolAddress((void**)&p_x,      g_x);
    cudaGetSymbolAddress((void**)&p_mid,    g_mid);
    cudaGetSymbolAddress((void**)&p_wqkvT,  g_wqkvT);
    cudaGetSymbolAddress((void**)&p_wprojT, g_wprojT);
    cudaGetSymbolAddress((void**)&p_w1T,    g_w1T);
    cudaGetSymbolAddress((void**)&p_w2T,    g_w2T);

    cudaFuncSetAttribute(fused_qkv_attn, cudaFuncAttributeMaxDynamicSharedMemorySize, FA_SMEM);
    cudaFuncSetAttribute(gemm_mma<3, true>,  cudaFuncAttributeMaxDynamicSharedMemorySize, G_SMEM);
    cudaFuncSetAttribute(gemm_mma<1, false>, cudaFuncAttributeMaxDynamicSharedMemorySize, G_SMEM);
    cudaFuncSetAttribute(gemm_mma<2, true>,  cudaFuncAttributeMaxDynamicSharedMemorySize, G_SMEM);

    // 1. merged ln1 + weight prep + counter reset (one launch)
    prep_kernel<<<16384 + 3072, 256>>>(feat, ln1_g, ln1_b, p_ln,
                                       w_qkv, w_proj, w1, w2,
                                       p_wqkvT, p_wprojT, p_w1T, p_w2T);
    // 2. fused qkv + attention -> g_attn (bf16, original order)
    fused_qkv_attn<<<P_TILES, 256, FA_SMEM>>>(p_ln, p_wqkvT, b_qkv, order, p_attn);
    // 3. proj + residual + fused LN2: x (f32) and ln2-out (bf16) in one kernel
    gemm_mma<3, true><<<dim3(2, N_TOK / 128), 256, G_SMEM>>>(
        p_attn, p_wprojT, b_proj, feat, p_x, N_TOK, C_DIM, C_DIM,
        ln2_g, ln2_b, p_ln);
    // 4. mid = gelu(ln2 @ w1 + b1)  — HW tanh.approx epilogue
    gemm_mma<1, false><<<dim3(8, N_TOK / 128), 256, G_SMEM>>>(
        p_ln, p_w1T, b1, nullptr, p_mid, N_TOK, HID_DIM, C_DIM,
        nullptr, nullptr, nullptr);
    // 5. out = x + mid @ w2 + b2  (f32)
    gemm_mma<2, true><<<dim3(2, N_TOK / 128), 256, G_SMEM>>>(
        p_mid, p_w2T, b2, p_x, (float*)d_out, N_TOK, C_DIM, HID_DIM,
        nullptr, nullptr, nullptr);
}